// round 8
// baseline (speedup 1.0000x reference)
#include <cuda_runtime.h>
#include <math.h>

#define PTS 4096      // B*N = 8*512

// ---------------- scratch (device globals) ----------------------------------
__device__ float g_pe[PTS * 256];
__device__ float g_spatial[PTS * 256];
__device__ float g_feat[PTS * 16];
__device__ float g_fe1[PTS * 128];
__device__ float g_h1[PTS * 128];
__device__ float g_fe2[PTS * 256];
__device__ float g_freq[PTS * 256];
__device__ float g_qkv[PTS * 256 * 3];   // q | k | v stacked
__device__ float g_o[PTS * 256];
__device__ float g_ao[PTS * 256];
__device__ float g_x[PTS * 256];
__device__ float g_ffh[PTS * 512];
__device__ float g_ff2[PTS * 256];
__device__ float g_x2[PTS * 256];

__device__ __forceinline__ float gelu_f(float x) {
    return 0.5f * x * (1.0f + erff(x * 0.7071067811865475f));
}

// ---- bf16x2 split helpers ---------------------------------------------------
// pack (x0,x1) into bf16x2: low half = x0, high half = x1.
// h = bf16 head pair, l = bf16 residual pair; x ~= h + l to ~16 mantissa bits.
__device__ __forceinline__ void packsplit(float x0, float x1,
                                          unsigned& h, unsigned& l) {
    unsigned hh;
    asm("cvt.rn.bf16x2.f32 %0, %1, %2;" : "=r"(hh) : "f"(x1), "f"(x0));
    float r0 = x0 - __uint_as_float(hh << 16);
    float r1 = x1 - __uint_as_float(hh & 0xffff0000u);
    asm("cvt.rn.bf16x2.f32 %0, %1, %2;" : "=r"(l) : "f"(r1), "f"(r0));
    h = hh;
}
__device__ __forceinline__ void mma16(float* c,
                                      unsigned a0, unsigned a1, unsigned a2, unsigned a3,
                                      unsigned b0, unsigned b1) {
    asm("mma.sync.aligned.m16n8k16.row.col.f32.bf16.bf16.f32 "
        "{%0,%1,%2,%3},{%4,%5,%6,%7},{%8,%9},{%0,%1,%2,%3};"
        : "+f"(c[0]), "+f"(c[1]), "+f"(c[2]), "+f"(c[3])
        : "r"(a0), "r"(a1), "r"(a2), "r"(a3), "r"(b0), "r"(b1));
}
// compensated product: C += Al*Bh + Ah*Bl + Ah*Bh
__device__ __forceinline__ void mma_x3(float* c,
                                       const unsigned ah[4], const unsigned al[4],
                                       unsigned bh0, unsigned bh1,
                                       unsigned bl0, unsigned bl1) {
    mma16(c, al[0], al[1], al[2], al[3], bh0, bh1);
    mma16(c, ah[0], ah[1], ah[2], ah[3], bl0, bl1);
    mma16(c, ah[0], ah[1], ah[2], ah[3], bh0, bh1);
}

// ---------------- PE kernel -------------------------------------------------
__global__ void __launch_bounds__(128) pe_kernel(const float* __restrict__ coords,
                                                 float* __restrict__ pe) {
    int pt = blockIdx.x, t = threadIdx.x;
    int i = t & 63, comp = t >> 6;
    float c = coords[pt * 2 + comp] * (1.0f / 1024.0f);
    float arg = c * 6.283185307179586f * exp2f(-(float)i * 0.4152410118609203f);
    float s, co;
    sincosf(arg, &s, &co);
    size_t base = (size_t)pt * 256 + (comp << 7) + i;
    pe[base] = s;
    pe[base + 64] = co;
}

// ---------------- patch gather + 2D DFT + radial binning --------------------
__global__ void __launch_bounds__(256) fft_feat_kernel(const float* __restrict__ image,
                                                       const float* __restrict__ coords,
                                                       const float* __restrict__ fbi,
                                                       float* __restrict__ feat) {
    int pt = blockIdx.x;
    int b = pt >> 9;
    int tid = threadIdx.x;

    __shared__ float patch[16][16];
    __shared__ float Rre[16][9], Rim[16][9];
    __shared__ float twc[16], tws[16];
    __shared__ float bmag[8], bang[8];
    __shared__ int bcnt[8];
    __shared__ float smf[8];
    __shared__ int spx, spy;

    if (tid == 0) {
        float cx = coords[pt * 2];
        float cy = coords[pt * 2 + 1];
        int px = (int)cx; px = min(max(px, 8), 1015);
        int py = (int)cy; py = min(max(py, 8), 1015);
        spx = px; spy = py;
        float mx = -1e30f;
        for (int i = 0; i < 8; i++) mx = fmaxf(mx, fbi[i]);
        float s = 0.0f;
        for (int i = 0; i < 8; i++) { float e = expf(fbi[i] - mx); smf[i] = e; s += e; }
        float inv = 1.0f / s;
        for (int i = 0; i < 8; i++) smf[i] *= inv;
    }
    if (tid < 16) {
        twc[tid] = cospif((float)tid / 8.0f);
        tws[tid] = sinpif(-(float)tid / 8.0f);
    }
    if (tid < 8) { bmag[tid] = 0.0f; bang[tid] = 0.0f; bcnt[tid] = 0; }
    __syncthreads();

    int y = tid >> 4, x = tid & 15;
    int yy = spy - 8 + y, xx = spx - 8 + x;
    const float* imb = image + (size_t)b * 3u * 1024u * 1024u;
    size_t off = (size_t)yy * 1024 + xx;
    float gsum = imb[off] + imb[1048576u + off] + imb[2097152u + off];
    patch[y][x] = gsum * (1.0f / 3.0f);
    __syncthreads();

    if (tid < 144) {
        int ry = tid / 9, kx = tid % 9;
        float re = 0.0f, im = 0.0f;
#pragma unroll
        for (int j = 0; j < 16; j++) {
            float pv = patch[ry][j];
            int t = (kx * j) & 15;
            re += pv * twc[t];
            im += pv * tws[t];
        }
        Rre[ry][kx] = re;
        Rim[ry][kx] = im;
    }
    __syncthreads();

    if (tid < 144) {
        int ky = tid / 9, kx = tid % 9;
        float re = 0.0f, im = 0.0f;
#pragma unroll
        for (int j = 0; j < 16; j++) {
            int t = (ky * j) & 15;
            float c = twc[t], s = tws[t];
            float ar = Rre[j][kx], ai = Rim[j][kx];
            re += ar * c - ai * s;
            im += ar * s + ai * c;
        }
        re *= 0.0625f;
        im *= 0.0625f;
        float mag = sqrtf(re * re + im * im);
        float ang = atan2f(im, re);

        double fy = (ky < 8) ? (double)ky / 16.0 : ((double)ky - 16.0) / 16.0;
        double fx = (double)kx / 16.0;
        double r = sqrt(fx * fx + fy * fy);
        double maxr = 0.7071067811865476 + 1e-6;
        double step = maxr / 8.0;
        int bi = 0;
#pragma unroll
        for (int k = 1; k < 9; k++) if (r >= (double)k * step) bi = k;
        if (bi > 7) bi = 7;
        atomicAdd(&bmag[bi], mag);
        atomicAdd(&bang[bi], ang);
        atomicAdd(&bcnt[bi], 1);
    }
    __syncthreads();

    if (tid < 8) {
        float c = (float)max(bcnt[tid], 1);
        feat[(size_t)pt * 16 + tid]     = bmag[tid] / c * smf[tid];
        feat[(size_t)pt * 16 + 8 + tid] = bang[tid] / c;
    }
}

// ---------------- bf16x2 tensor GEMM: C = A @ B^T + bias --------------------
// 64x64 tile, 128 threads (2x2 warp tiles of 32x32), double-buffered,
// hi/lo packed in smem at stage time.
// EP: 0 bias, 1 bias+gelu, 2 bias+type_emb. QKV: z selects A/W/bias/C slice.
template <int EP, bool QKV>
__global__ void __launch_bounds__(128) gemm_bf(
    const float* __restrict__ A, const float* __restrict__ B,
    const float* __restrict__ bias, float* __restrict__ C,
    int K, int lda, int ldb, int ldc,
    const int* __restrict__ labels, const float* __restrict__ temb,
    const float* __restrict__ A2)
{
    __shared__ unsigned Ah[2][8][72], Al[2][8][72];
    __shared__ unsigned Bh[2][8][72], Bl[2][8][72];

    if (QKV) {
        const int z = blockIdx.z;
        if (z > 0) A = A2;
        B += (size_t)z * 65536;
        bias += z << 8;
        C += (size_t)z * (PTS * 256);
    }

    const int tid = threadIdx.x;
    const int m0 = blockIdx.y << 6, n0 = blockIdx.x << 6;

    const int arow = tid >> 1;              // 0..63
    const int k2b = (tid & 1) << 2;         // k2 base 0 or 4 (k byte offset 0/8)
    const float* Aptr = A + (size_t)(m0 + arow) * lda + (k2b << 1);
    const float* Bptr = B + (size_t)(n0 + arow) * ldb + (k2b << 1);

    const int lane = tid & 31, wid = tid >> 5;
    const int g = lane >> 2, t4 = lane & 3;
    const int wm = (wid >> 1) << 5;
    const int wn = (wid & 1) << 5;

    float acc[2][4][4] = {};

    // stage tile 0
    {
        float4 a0 = *(const float4*)Aptr;
        float4 a1 = *(const float4*)(Aptr + 4);
        packsplit(a0.x, a0.y, Ah[0][k2b + 0][arow], Al[0][k2b + 0][arow]);
        packsplit(a0.z, a0.w, Ah[0][k2b + 1][arow], Al[0][k2b + 1][arow]);
        packsplit(a1.x, a1.y, Ah[0][k2b + 2][arow], Al[0][k2b + 2][arow]);
        packsplit(a1.z, a1.w, Ah[0][k2b + 3][arow], Al[0][k2b + 3][arow]);
        float4 b0 = *(const float4*)Bptr;
        float4 b1 = *(const float4*)(Bptr + 4);
        packsplit(b0.x, b0.y, Bh[0][k2b + 0][arow], Bl[0][k2b + 0][arow]);
        packsplit(b0.z, b0.w, Bh[0][k2b + 1][arow], Bl[0][k2b + 1][arow]);
        packsplit(b1.x, b1.y, Bh[0][k2b + 2][arow], Bl[0][k2b + 2][arow]);
        packsplit(b1.z, b1.w, Bh[0][k2b + 3][arow], Bl[0][k2b + 3][arow]);
    }
    __syncthreads();

    int buf = 0;
    for (int k0 = 0; k0 < K; k0 += 16) {
        const bool notlast = (k0 + 16 < K);
        float4 pa0, pa1, pb0, pb1;
        if (notlast) {
            pa0 = *(const float4*)(Aptr + k0 + 16);
            pa1 = *(const float4*)(Aptr + k0 + 20);
            pb0 = *(const float4*)(Bptr + k0 + 16);
            pb1 = *(const float4*)(Bptr + k0 + 20);
        }

        // one m16n8k16 k-step over the 16-wide tile
        unsigned ah[2][4], al[2][4];
#pragma unroll
        for (int mi = 0; mi < 2; mi++) {
            int r0 = wm + mi * 16 + g, r1 = r0 + 8;
            ah[mi][0] = Ah[buf][t4][r0];     al[mi][0] = Al[buf][t4][r0];
            ah[mi][1] = Ah[buf][t4][r1];     al[mi][1] = Al[buf][t4][r1];
            ah[mi][2] = Ah[buf][t4 + 4][r0]; al[mi][2] = Al[buf][t4 + 4][r0];
            ah[mi][3] = Ah[buf][t4 + 4][r1]; al[mi][3] = Al[buf][t4 + 4][r1];
        }
#pragma unroll
        for (int ni = 0; ni < 4; ni++) {
            int c = wn + ni * 8 + g;
            unsigned bh0 = Bh[buf][t4][c],     bl0 = Bl[buf][t4][c];
            unsigned bh1 = Bh[buf][t4 + 4][c], bl1 = Bl[buf][t4 + 4][c];
#pragma unroll
            for (int mi = 0; mi < 2; mi++)
                mma_x3(acc[mi][ni], ah[mi], al[mi], bh0, bh1, bl0, bl1);
        }

        if (notlast) {
            int nb = buf ^ 1;
            packsplit(pa0.x, pa0.y, Ah[nb][k2b + 0][arow], Al[nb][k2b + 0][arow]);
            packsplit(pa0.z, pa0.w, Ah[nb][k2b + 1][arow], Al[nb][k2b + 1][arow]);
            packsplit(pa1.x, pa1.y, Ah[nb][k2b + 2][arow], Al[nb][k2b + 2][arow]);
            packsplit(pa1.z, pa1.w, Ah[nb][k2b + 3][arow], Al[nb][k2b + 3][arow]);
            packsplit(pb0.x, pb0.y, Bh[nb][k2b + 0][arow], Bl[nb][k2b + 0][arow]);
            packsplit(pb0.z, pb0.w, Bh[nb][k2b + 1][arow], Bl[nb][k2b + 1][arow]);
            packsplit(pb1.x, pb1.y, Bh[nb][k2b + 2][arow], Bl[nb][k2b + 2][arow]);
            packsplit(pb1.z, pb1.w, Bh[nb][k2b + 3][arow], Bl[nb][k2b + 3][arow]);
            __syncthreads();
            buf = nb;
        }
    }

#pragma unroll
    for (int mi = 0; mi < 2; mi++) {
        int r0 = m0 + wm + mi * 16 + g;
        int r1 = r0 + 8;
        const float* t0 = nullptr;
        const float* t1 = nullptr;
        if (EP == 2) {
            t0 = temb + (size_t)labels[r0] * 256;
            t1 = temb + (size_t)labels[r1] * 256;
        }
#pragma unroll
        for (int ni = 0; ni < 4; ni++) {
            int c0 = n0 + wn + ni * 8 + (t4 << 1);
            float v00 = acc[mi][ni][0], v01 = acc[mi][ni][1];
            float v10 = acc[mi][ni][2], v11 = acc[mi][ni][3];
            float bx = bias[c0], by = bias[c0 + 1];
            v00 += bx; v01 += by; v10 += bx; v11 += by;
            if (EP == 1) {
                v00 = gelu_f(v00); v01 = gelu_f(v01);
                v10 = gelu_f(v10); v11 = gelu_f(v11);
            }
            if (EP == 2) {
                v00 += t0[c0]; v01 += t0[c0 + 1];
                v10 += t1[c0]; v11 += t1[c0 + 1];
            }
            *(float2*)(C + (size_t)r0 * ldc + c0) = make_float2(v00, v01);
            *(float2*)(C + (size_t)r1 * ldc + c0) = make_float2(v10, v11);
        }
    }
}

// ---------------- fused attention (flash-style, bf16x2) ---------------------
// grid (8 q-tiles, 4 heads, 8 batch), 128 threads.
__global__ void __launch_bounds__(128) attn_fused(const float* __restrict__ QKVb,
                                                  float* __restrict__ O) {
    __shared__ unsigned Qh[32][72], Ql[32][72];   // [d2][qrow]
    __shared__ unsigned Kh[32][40], Kl[32][40];   // [d2][kpos]
    __shared__ unsigned Vh[16][72], Vl[16][72];   // [k2][d]
    __shared__ unsigned Ph[16][72], Pl[16][72];   // [k2][qrow]
    __shared__ float rm[64], rl[64], rf[64];

    const int b = blockIdx.z, h = blockIdx.y, q0 = blockIdx.x << 6;
    const int tid = threadIdx.x;
    const int lane = tid & 31, wid = tid >> 5;
    const int g = lane >> 2, t4 = lane & 3;

    const float* Qg = QKVb + ((size_t)(b * 512 + q0)) * 256 + h * 64;
    const float* Kg = QKVb + (size_t)PTS * 256 + ((size_t)b * 512) * 256 + h * 64;
    const float* Vg = QKVb + (size_t)PTS * 512 + ((size_t)b * 512) * 256 + h * 64;

    {   // load + pack Q tile
        int qrow = tid >> 1, d0 = (tid & 1) << 5;
        const float* src = Qg + (size_t)qrow * 256 + d0;
#pragma unroll
        for (int j = 0; j < 8; j++) {
            float4 v = *(const float4*)(src + j * 4);
            int k2 = (d0 >> 1) + 2 * j;
            packsplit(v.x, v.y, Qh[k2][qrow],     Ql[k2][qrow]);
            packsplit(v.z, v.w, Qh[k2 + 1][qrow], Ql[k2 + 1][qrow]);
        }
    }
    if (tid < 64) { rm[tid] = -1e30f; rl[tid] = 0.0f; }

    const int wm = (wid >> 1) << 5, wn = (wid & 1) << 5;
    const int sm = wid << 4;     // S-phase: warp owns 16 q-rows
    float oacc[2][4][4] = {};

    for (int kc = 0; kc < 512; kc += 32) {
        __syncthreads();
        {   // stage K packed (pairs along d)
            int kpos = tid >> 2, d0 = (tid & 3) << 4;
            const float* ks = Kg + (size_t)(kc + kpos) * 256 + d0;
#pragma unroll
            for (int j = 0; j < 4; j++) {
                float4 v = *(const float4*)(ks + j * 4);
                int k2 = (d0 >> 1) + 2 * j;
                packsplit(v.x, v.y, Kh[k2][kpos],     Kl[k2][kpos]);
                packsplit(v.z, v.w, Kh[k2 + 1][kpos], Kl[k2 + 1][kpos]);
            }
        }
        {   // stage V packed (pairs along kpos)
            int k2 = tid >> 3, d0 = (tid & 7) << 3;
            const float* v0p = Vg + (size_t)(kc + 2 * k2) * 256 + d0;
            const float* v1p = v0p + 256;
            float4 a0 = *(const float4*)v0p, a1 = *(const float4*)(v0p + 4);
            float4 b0 = *(const float4*)v1p, b1 = *(const float4*)(v1p + 4);
            packsplit(a0.x, b0.x, Vh[k2][d0 + 0], Vl[k2][d0 + 0]);
            packsplit(a0.y, b0.y, Vh[k2][d0 + 1], Vl[k2][d0 + 1]);
            packsplit(a0.z, b0.z, Vh[k2][d0 + 2], Vl[k2][d0 + 2]);
            packsplit(a0.w, b0.w, Vh[k2][d0 + 3], Vl[k2][d0 + 3]);
            packsplit(a1.x, b1.x, Vh[k2][d0 + 4], Vl[k2][d0 + 4]);
            packsplit(a1.y, b1.y, Vh[k2][d0 + 5], Vl[k2][d0 + 5]);
            packsplit(a1.z, b1.z, Vh[k2][d0 + 6], Vl[k2][d0 + 6]);
            packsplit(a1.w, b1.w, Vh[k2][d0 + 7], Vl[k2][d0 + 7]);
        }
        __syncthreads();

        // S = Q K^T (warp computes 16 rows x 32 cols)
        float sacc[4][4] = {};
#pragma unroll
        for (int kk2 = 0; kk2 < 32; kk2 += 8) {
            unsigned ah[4], al[4];
            int r0 = sm + g, r1 = r0 + 8;
            ah[0] = Qh[kk2 + t4][r0];     al[0] = Ql[kk2 + t4][r0];
            ah[1] = Qh[kk2 + t4][r1];     al[1] = Ql[kk2 + t4][r1];
            ah[2] = Qh[kk2 + t4 + 4][r0]; al[2] = Ql[kk2 + t4 + 4][r0];
            ah[3] = Qh[kk2 + t4 + 4][r1]; al[3] = Ql[kk2 + t4 + 4][r1];
#pragma unroll
            for (int ni = 0; ni < 4; ni++) {
                int c = ni * 8 + g;
                unsigned bh0 = Kh[kk2 + t4][c],     bl0 = Kl[kk2 + t4][c];
                unsigned bh1 = Kh[kk2 + t4 + 4][c], bl1 = Kl[kk2 + t4 + 4][c];
                mma_x3(sacc[ni], ah, al, bh0, bh1, bl0, bl1);
            }
        }

        // in-register online softmax for rows sm+g, sm+g+8
        {
            int r0 = sm + g, r1 = r0 + 8;
            float mx0 = -1e30f, mx1 = -1e30f;
#pragma unroll
            for (int ni = 0; ni < 4; ni++) {
                sacc[ni][0] *= 0.125f; sacc[ni][1] *= 0.125f;
                sacc[ni][2] *= 0.125f; sacc[ni][3] *= 0.125f;
                mx0 = fmaxf(mx0, fmaxf(sacc[ni][0], sacc[ni][1]));
                mx1 = fmaxf(mx1, fmaxf(sacc[ni][2], sacc[ni][3]));
            }
            mx0 = fmaxf(mx0, __shfl_xor_sync(0xffffffffu, mx0, 1));
            mx0 = fmaxf(mx0, __shfl_xor_sync(0xffffffffu, mx0, 2));
            mx1 = fmaxf(mx1, __shfl_xor_sync(0xffffffffu, mx1, 1));
            mx1 = fmaxf(mx1, __shfl_xor_sync(0xffffffffu, mx1, 2));
            float mo0 = rm[r0], mo1 = rm[r1];
            float mn0 = fmaxf(mo0, mx0), mn1 = fmaxf(mo1, mx1);
            float f0 = __expf(mo0 - mn0), f1 = __expf(mo1 - mn1);
            float sum0 = 0.0f, sum1 = 0.0f;
            float p[4][4];
#pragma unroll
            for (int ni = 0; ni < 4; ni++) {
                p[ni][0] = __expf(sacc[ni][0] - mn0);
                p[ni][1] = __expf(sacc[ni][1] - mn0);
                p[ni][2] = __expf(sacc[ni][2] - mn1);
                p[ni][3] = __expf(sacc[ni][3] - mn1);
                sum0 += p[ni][0] + p[ni][1];
                sum1 += p[ni][2] + p[ni][3];
            }
            sum0 += __shfl_xor_sync(0xffffffffu, sum0, 1);
            sum0 += __shfl_xor_sync(0xffffffffu, sum0, 2);
            sum1 += __shfl_xor_sync(0xffffffffu, sum1, 1);
            sum1 += __shfl_xor_sync(0xffffffffu, sum1, 2);
            if (t4 == 0) {
                rl[r0] = rl[r0] * f0 + sum0; rm[r0] = mn0; rf[r0] = f0;
                rl[r1] = rl[r1] * f1 + sum1; rm[r1] = mn1; rf[r1] = f1;
            }
            // pack P (rows r0/r1, k2 = ni*4 + t4)
#pragma unroll
            for (int ni = 0; ni < 4; ni++) {
                int k2 = ni * 4 + t4;
                packsplit(p[ni][0], p[ni][1], Ph[k2][r0], Pl[k2][r0]);
                packsplit(p[ni][2], p[ni][3], Ph[k2][r1], Pl[k2][r1]);
            }
        }
        __syncthreads();

        // rescale accumulators, then O += P V
#pragma unroll
        for (int mi = 0; mi < 2; mi++) {
            float f0 = rf[wm + (mi << 4) + g];
            float f1 = rf[wm + (mi << 4) + g + 8];
#pragma unroll
            for (int ni = 0; ni < 4; ni++) {
                oacc[mi][ni][0] *= f0; oacc[mi][ni][1] *= f0;
                oacc[mi][ni][2] *= f1; oacc[mi][ni][3] *= f1;
            }
        }
#pragma unroll
        for (int kk2 = 0; kk2 < 16; kk2 += 8) {
            unsigned ah[2][4], al[2][4];
#pragma unroll
            for (int mi = 0; mi < 2; mi++) {
                int r0 = wm + (mi << 4) + g, r1 = r0 + 8;
                ah[mi][0] = Ph[kk2 + t4][r0];     al[mi][0] = Pl[kk2 + t4][r0];
                ah[mi][1] = Ph[kk2 + t4][r1];     al[mi][1] = Pl[kk2 + t4][r1];
                ah[mi][2] = Ph[kk2 + t4 + 4][r0]; al[mi][2] = Pl[kk2 + t4 + 4][r0];
                ah[mi][3] = Ph[kk2 + t4 + 4][r1]; al[mi][3] = Pl[kk2 + t4 + 4][r1];
            }
#pragma unroll
            for (int ni = 0; ni < 4; ni++) {
                int c = wn + ni * 8 + g;
                unsigned bh0 = Vh[kk2 + t4][c],     bl0 = Vl[kk2 + t4][c];
                unsigned bh1 = Vh[kk2 + t4 + 4][c], bl1 = Vl[kk2 + t4 + 4][c];
#pragma unroll
                for (int mi = 0; mi < 2; mi++)
                    mma_x3(oacc[mi][ni], ah[mi], al[mi], bh0, bh1, bl0, bl1);
            }
        }
    }

    float* Og = O + ((size_t)(b * 512 + q0)) * 256 + h * 64;
#pragma unroll
    for (int mi = 0; mi < 2; mi++) {
        int r0 = wm + (mi << 4) + g, r1 = r0 + 8;
        float il0 = 1.0f / rl[r0], il1 = 1.0f / rl[r1];
#pragma unroll
        for (int ni = 0; ni < 4; ni++) {
            int c = wn + (ni << 3) + (t4 << 1);
            *(float2*)(Og + (size_t)r0 * 256 + c) =
                make_float2(oacc[mi][ni][0] * il0, oacc[mi][ni][1] * il0);
            *(float2*)(Og + (size_t)r1 * 256 + c) =
                make_float2(oacc[mi][ni][2] * il1, oacc[mi][ni][3] * il1);
        }
    }
}

// ---------------- layer norm: warp per row ----------------------------------
template <int WIDTH, bool GELU, bool RES>
__global__ void __launch_bounds__(128) ln_warp(const float* __restrict__ in,
                                               const float* __restrict__ res,
                                               const float* __restrict__ g,
                                               const float* __restrict__ bv,
                                               float* __restrict__ out) {
    const int V4 = WIDTH / 128;
    int w = threadIdx.x >> 5, lane = threadIdx.x & 31;
    int row = (blockIdx.x << 2) + w;
    const float4* ip = (const float4*)(in + (size_t)row * WIDTH);
    const float4* rp = (const float4*)(res + (size_t)row * WIDTH);
    float4 v[V4];
    float s = 0.0f;
#pragma unroll
    for (int i = 0; i < V4; i++) {
        v[i] = ip[lane + 32 * i];
        if (RES) {
            float4 r = rp[lane + 32 * i];
            v[i].x += r.x; v[i].y += r.y; v[i].z += r.z; v[i].w += r.w;
        }
        s += v[i].x + v[i].y + v[i].z + v[i].w;
    }
#pragma unroll
    for (int o = 16; o; o >>= 1) s += __shfl_xor_sync(0xffffffffu, s, o);
    float mean = s * (1.0f / WIDTH);
    float q = 0.0f;
#pragma unroll
    for (int i = 0; i < V4; i++) {
        v[i].x -= mean; v[i].y -= mean; v[i].z -= mean; v[i].w -= mean;
        q += v[i].x * v[i].x + v[i].y * v[i].y + v[i].z * v[i].z + v[i].w * v[i].w;
    }
#pragma unroll
    for (int o = 16; o; o >>= 1) q += __shfl_xor_sync(0xffffffffu, q, o);
    float inv = rsqrtf(q * (1.0f / WIDTH) + 1e-5f);
    const float4* gp = (const float4*)g;
    const float4* bp = (const float4*)bv;
    float4* op = (float4*)(out + (size_t)row * WIDTH);
#pragma unroll
    for (int i = 0; i < V4; i++) {
        float4 gg = gp[lane + 32 * i], bb = bp[lane + 32 * i];
        float4 o;
        o.x = gg.x * v[i].x * inv + bb.x;
        o.y = gg.y * v[i].y * inv + bb.y;
        o.z = gg.z * v[i].z * inv + bb.z;
        o.w = gg.w * v[i].w * inv + bb.w;
        if (GELU) {
            o.x = gelu_f(o.x); o.y = gelu_f(o.y);
            o.z = gelu_f(o.z); o.w = gelu_f(o.w);
        }
        op[lane + 32 * i] = o;
    }
}

// ---------------- launch ----------------------------------------------------
extern "C" void kernel_launch(void* const* d_in, const int* in_sizes, int n_in,
                              void* d_out, int out_size) {
    (void)in_sizes; (void)n_in; (void)out_size;
    const float* image  = (const float*)d_in[0];
    const float* coords = (const float*)d_in[1];
    const int*   labels = (const int*)d_in[2];
    const float* pe_w   = (const float*)d_in[3];
    const float* pe_b   = (const float*)d_in[4];
    const float* temb   = (const float*)d_in[5];
    const float* fbi    = (const float*)d_in[6];
    const float* fe1_w  = (const float*)d_in[7];
    const float* fe1_b  = (const float*)d_in[8];
    const float* feln1g = (const float*)d_in[9];
    const float* feln1b = (const float*)d_in[10];
    const float* fe2_w  = (const float*)d_in[11];
    const float* fe2_b  = (const float*)d_in[12];
    const float* feln2g = (const float*)d_in[13];
    const float* feln2b = (const float*)d_in[14];
    const float* in_w   = (const float*)d_in[15];
    const float* in_b   = (const float*)d_in[16];
    const float* ao_w   = (const float*)d_in[17];
    const float* ao_b   = (const float*)d_in[18];
    const float* n1_g   = (const float*)d_in[19];
    const float* n1_b   = (const float*)d_in[20];
    const float* f1_w   = (const float*)d_in[21];
    const float* f1_b   = (const float*)d_in[22];
    const float* f2_w   = (const float*)d_in[23];
    const float* f2_b   = (const float*)d_in[24];
    const float* n2_g   = (const float*)d_in[25];
    const float* n2_b   = (const float*)d_in[26];
    const float* op_w   = (const float*)d_in[27];
    const float* op_b   = (const float*)d_in[28];
    float* out = (float*)d_out;

    float *p_pe, *p_spatial, *p_feat, *p_fe1, *p_h1, *p_fe2, *p_freq;
    float *p_qkv, *p_o, *p_ao, *p_x, *p_ffh, *p_ff2, *p_x2;
    cudaGetSymbolAddress((void**)&p_pe, g_pe);
    cudaGetSymbolAddress((void**)&p_spatial, g_spatial);
    cudaGetSymbolAddress((void**)&p_feat, g_feat);
    cudaGetSymbolAddress((void**)&p_fe1, g_fe1);
    cudaGetSymbolAddress((void**)&p_h1, g_h1);
    cudaGetSymbolAddress((void**)&p_fe2, g_fe2);
    cudaGetSymbolAddress((void**)&p_freq, g_freq);
    cudaGetSymbolAddress((void**)&p_qkv, g_qkv);
    cudaGetSymbolAddress((void**)&p_o, g_o);
    cudaGetSymbolAddress((void**)&p_ao, g_ao);
    cudaGetSymbolAddress((void**)&p_x, g_x);
    cudaGetSymbolAddress((void**)&p_ffh, g_ffh);
    cudaGetSymbolAddress((void**)&p_ff2, g_ff2);
    cudaGetSymbolAddress((void**)&p_x2, g_x2);

    // 1) sinusoidal PE
    pe_kernel<<<PTS, 128>>>(coords, p_pe);
    // 2) spatial = PE @ pe_w^T + pe_b + type_emb[label]
    gemm_bf<2, false><<<dim3(4, 64, 1), 128>>>(p_pe, pe_w, pe_b, p_spatial,
        256, 256, 256, 256, labels, temb, nullptr);
    // 3) patch FFT features
    fft_feat_kernel<<<PTS, 256>>>(image, coords, fbi, p_feat);
    // 4) freq MLP
    gemm_bf<0, false><<<dim3(2, 64, 1), 128>>>(p_feat, fe1_w, fe1_b, p_fe1,
        16, 16, 16, 128, nullptr, nullptr, nullptr);
    ln_warp<128, true, false><<<PTS / 4, 128>>>(p_fe1, p_fe1, feln1g, feln1b, p_h1);
    gemm_bf<0, false><<<dim3(4, 64, 1), 128>>>(p_h1, fe2_w, fe2_b, p_fe2,
        128, 128, 128, 256, nullptr, nullptr, nullptr);
    ln_warp<256, false, false><<<PTS / 4, 128>>>(p_fe2, p_fe2, feln2g, feln2b, p_freq);
    // 5) fused Q/K/V projections (z = 0,1,2)
    gemm_bf<0, true><<<dim3(4, 64, 3), 128>>>(p_spatial, in_w, in_b, p_qkv,
        256, 256, 256, 256, nullptr, nullptr, p_freq);
    // 6) fused attention
    attn_fused<<<dim3(8, 4, 8), 128>>>(p_qkv, p_o);
    // 7) attn out proj + residual LN
    gemm_bf<0, false><<<dim3(4, 64, 1), 128>>>(p_o, ao_w, ao_b, p_ao,
        256, 256, 256, 256, nullptr, nullptr, nullptr);
    ln_warp<256, false, true><<<PTS / 4, 128>>>(p_ao, p_spatial, n1_g, n1_b, p_x);
    // 8) FFN
    gemm_bf<1, false><<<dim3(8, 64, 1), 128>>>(p_x, f1_w, f1_b, p_ffh,
        256, 256, 256, 512, nullptr, nullptr, nullptr);
    gemm_bf<0, false><<<dim3(4, 64, 1), 128>>>(p_ffh, f2_w, f2_b, p_ff2,
        512, 512, 512, 256, nullptr, nullptr, nullptr);
    ln_warp<256, false, true><<<PTS / 4, 128>>>(p_ff2, p_x, n2_g, n2_b, p_x2);
    // 9) output projection
    gemm_bf<0, false><<<dim3(4, 64, 1), 128>>>(p_x2, op_w, op_b, out,
        256, 256, 256, 256, nullptr, nullptr, nullptr);
}

// round 9
// speedup vs baseline: 1.2959x; 1.2959x over previous
#include <cuda_runtime.h>
#include <math.h>

#define PTS 4096      // B*N = 8*512

// ---------------- scratch (device globals) ----------------------------------
__device__ float g_pe[PTS * 256];
__device__ float g_spatial[PTS * 256];
__device__ float g_feat[PTS * 16];
__device__ float g_fe1[PTS * 128];
__device__ float g_h1[PTS * 128];
__device__ float g_fe2[PTS * 256];
__device__ float g_freq[PTS * 256];
__device__ unsigned g_qkh[2u * PTS * 128];  // packed bf16 hi: Q | K (d-pairs)
__device__ unsigned g_qkl[2u * PTS * 128];  // packed bf16 lo
__device__ float g_v[PTS * 256];
__device__ float g_o[PTS * 256];
__device__ float g_ao[PTS * 256];
__device__ float g_x[PTS * 256];
__device__ float g_ffh[PTS * 512];
__device__ float g_ff2[PTS * 256];
__device__ float g_x2[PTS * 256];

__device__ __forceinline__ float gelu_f(float x) {
    return 0.5f * x * (1.0f + erff(x * 0.7071067811865475f));
}

// tf32 helpers ---------------------------------------------------------------
__device__ __forceinline__ unsigned tf32_rna(float x) {
    unsigned r;
    asm("cvt.rna.tf32.f32 %0, %1;" : "=r"(r) : "f"(x));
    return r;
}
__device__ __forceinline__ void mma8(float* c, unsigned a0, unsigned a1,
                                     unsigned a2, unsigned a3,
                                     unsigned b0, unsigned b1) {
    asm("mma.sync.aligned.m16n8k8.row.col.f32.tf32.tf32.f32 "
        "{%0,%1,%2,%3},{%4,%5,%6,%7},{%8,%9},{%0,%1,%2,%3};"
        : "+f"(c[0]), "+f"(c[1]), "+f"(c[2]), "+f"(c[3])
        : "r"(a0), "r"(a1), "r"(a2), "r"(a3), "r"(b0), "r"(b1));
}
__device__ __forceinline__ void split_tf32(float x, unsigned& hi, unsigned& lo) {
    hi = tf32_rna(x);
    lo = __float_as_uint(x - __uint_as_float(hi));
}

// bf16x2 helpers --------------------------------------------------------------
// pack (x0,x1): lo half = x0 (k even), hi half = x1 (k odd)
__device__ __forceinline__ void packsplit(float x0, float x1,
                                          unsigned& h, unsigned& l) {
    unsigned hh;
    asm("cvt.rn.bf16x2.f32 %0, %1, %2;" : "=r"(hh) : "f"(x1), "f"(x0));
    float r0 = x0 - __uint_as_float(hh << 16);
    float r1 = x1 - __uint_as_float(hh & 0xffff0000u);
    asm("cvt.rn.bf16x2.f32 %0, %1, %2;" : "=r"(l) : "f"(r1), "f"(r0));
    h = hh;
}
__device__ __forceinline__ void mma16(float* c,
                                      unsigned a0, unsigned a1, unsigned a2, unsigned a3,
                                      unsigned b0, unsigned b1) {
    asm("mma.sync.aligned.m16n8k16.row.col.f32.bf16.bf16.f32 "
        "{%0,%1,%2,%3},{%4,%5,%6,%7},{%8,%9},{%0,%1,%2,%3};"
        : "+f"(c[0]), "+f"(c[1]), "+f"(c[2]), "+f"(c[3])
        : "r"(a0), "r"(a1), "r"(a2), "r"(a3), "r"(b0), "r"(b1));
}

// ---------------- PE kernel -------------------------------------------------
__global__ void __launch_bounds__(128) pe_kernel(const float* __restrict__ coords,
                                                 float* __restrict__ pe) {
    int pt = blockIdx.x, t = threadIdx.x;
    int i = t & 63, comp = t >> 6;
    float c = coords[pt * 2 + comp] * (1.0f / 1024.0f);
    float arg = c * 6.283185307179586f * exp2f(-(float)i * 0.4152410118609203f);
    float s, co;
    sincosf(arg, &s, &co);
    size_t base = (size_t)pt * 256 + (comp << 7) + i;
    pe[base] = s;
    pe[base + 64] = co;
}

// ---------------- patch gather + 2D DFT + radial binning --------------------
__global__ void __launch_bounds__(256) fft_feat_kernel(const float* __restrict__ image,
                                                       const float* __restrict__ coords,
                                                       const float* __restrict__ fbi,
                                                       float* __restrict__ feat) {
    int pt = blockIdx.x;
    int b = pt >> 9;
    int tid = threadIdx.x;

    __shared__ float patch[16][16];
    __shared__ float Rre[16][9], Rim[16][9];
    __shared__ float twc[16], tws[16];
    __shared__ float bmag[8], bang[8];
    __shared__ int bcnt[8];
    __shared__ float smf[8];
    __shared__ int spx, spy;

    if (tid == 0) {
        float cx = coords[pt * 2];
        float cy = coords[pt * 2 + 1];
        int px = (int)cx; px = min(max(px, 8), 1015);
        int py = (int)cy; py = min(max(py, 8), 1015);
        spx = px; spy = py;
        float mx = -1e30f;
        for (int i = 0; i < 8; i++) mx = fmaxf(mx, fbi[i]);
        float s = 0.0f;
        for (int i = 0; i < 8; i++) { float e = expf(fbi[i] - mx); smf[i] = e; s += e; }
        float inv = 1.0f / s;
        for (int i = 0; i < 8; i++) smf[i] *= inv;
    }
    if (tid < 16) {
        twc[tid] = cospif((float)tid / 8.0f);
        tws[tid] = sinpif(-(float)tid / 8.0f);
    }
    if (tid < 8) { bmag[tid] = 0.0f; bang[tid] = 0.0f; bcnt[tid] = 0; }
    __syncthreads();

    int y = tid >> 4, x = tid & 15;
    int yy = spy - 8 + y, xx = spx - 8 + x;
    const float* imb = image + (size_t)b * 3u * 1024u * 1024u;
    size_t off = (size_t)yy * 1024 + xx;
    float gsum = imb[off] + imb[1048576u + off] + imb[2097152u + off];
    patch[y][x] = gsum * (1.0f / 3.0f);
    __syncthreads();

    if (tid < 144) {
        int ry = tid / 9, kx = tid % 9;
        float re = 0.0f, im = 0.0f;
#pragma unroll
        for (int j = 0; j < 16; j++) {
            float pv = patch[ry][j];
            int t = (kx * j) & 15;
            re += pv * twc[t];
            im += pv * tws[t];
        }
        Rre[ry][kx] = re;
        Rim[ry][kx] = im;
    }
    __syncthreads();

    if (tid < 144) {
        int ky = tid / 9, kx = tid % 9;
        float re = 0.0f, im = 0.0f;
#pragma unroll
        for (int j = 0; j < 16; j++) {
            int t = (ky * j) & 15;
            float c = twc[t], s = tws[t];
            float ar = Rre[j][kx], ai = Rim[j][kx];
            re += ar * c - ai * s;
            im += ar * s + ai * c;
        }
        re *= 0.0625f;
        im *= 0.0625f;
        float mag = sqrtf(re * re + im * im);
        float ang = atan2f(im, re);

        double fy = (ky < 8) ? (double)ky / 16.0 : ((double)ky - 16.0) / 16.0;
        double fx = (double)kx / 16.0;
        double r = sqrt(fx * fx + fy * fy);
        double maxr = 0.7071067811865476 + 1e-6;
        double step = maxr / 8.0;
        int bi = 0;
#pragma unroll
        for (int k = 1; k < 9; k++) if (r >= (double)k * step) bi = k;
        if (bi > 7) bi = 7;
        atomicAdd(&bmag[bi], mag);
        atomicAdd(&bang[bi], ang);
        atomicAdd(&bcnt[bi], 1);
    }
    __syncthreads();

    if (tid < 8) {
        float c = (float)max(bcnt[tid], 1);
        feat[(size_t)pt * 16 + tid]     = bmag[tid] / c * smf[tid];
        feat[(size_t)pt * 16 + 8 + tid] = bang[tid] / c;
    }
}

// ---------------- tensor-core GEMM (tf32 x3): C = A @ B^T + bias ------------
// 64x64 tile, 128 threads (2x2 warp tiles of 32x32), double-buffered.
// EP: 0 bias, 1 bias+gelu, 2 bias+type_emb, 4 QKV (z<2 packed bf16 out, z=2 float).
template <int EP>
__global__ void __launch_bounds__(128) gemm_tc(
    const float* __restrict__ A, const float* __restrict__ B,
    const float* __restrict__ bias, float* __restrict__ C,
    int K, int lda, int ldb, int ldc,
    const int* __restrict__ labels, const float* __restrict__ temb,
    const float* __restrict__ A2,
    unsigned* __restrict__ uh, unsigned* __restrict__ ul)
{
    __shared__ __align__(16) float As[2][16][72];
    __shared__ __align__(16) float Bs[2][16][72];

    if (EP == 4) {
        const int z = blockIdx.z;
        if (z > 0) A = A2;
        B += (size_t)z * 65536;
        bias += z << 8;
    }

    const int tid = threadIdx.x;
    const int m0 = blockIdx.y << 6, n0 = blockIdx.x << 6;

    const int arow = tid >> 1, ak = (tid & 1) << 3;       // 64 rows x 16 k
    const float* Aptr = A + (size_t)(m0 + arow) * lda + ak;
    const float* Bptr = B + (size_t)(n0 + arow) * ldb + ak;

    const int lane = tid & 31, wid = tid >> 5;
    const int g = lane >> 2, t4 = lane & 3;
    const int wm = (wid >> 1) << 5;
    const int wn = (wid & 1) << 5;

    float acc[2][4][4] = {};

    {
        float4 a0 = *(const float4*)Aptr;
        float4 a1 = *(const float4*)(Aptr + 4);
        As[0][ak + 0][arow] = a0.x; As[0][ak + 1][arow] = a0.y;
        As[0][ak + 2][arow] = a0.z; As[0][ak + 3][arow] = a0.w;
        As[0][ak + 4][arow] = a1.x; As[0][ak + 5][arow] = a1.y;
        As[0][ak + 6][arow] = a1.z; As[0][ak + 7][arow] = a1.w;
        float4 b0 = *(const float4*)Bptr;
        float4 b1 = *(const float4*)(Bptr + 4);
        Bs[0][ak + 0][arow] = b0.x; Bs[0][ak + 1][arow] = b0.y;
        Bs[0][ak + 2][arow] = b0.z; Bs[0][ak + 3][arow] = b0.w;
        Bs[0][ak + 4][arow] = b1.x; Bs[0][ak + 5][arow] = b1.y;
        Bs[0][ak + 6][arow] = b1.z; Bs[0][ak + 7][arow] = b1.w;
    }
    __syncthreads();

    int buf = 0;
    for (int k0 = 0; k0 < K; k0 += 16) {
        const bool notlast = (k0 + 16 < K);
        float4 pa0, pa1, pb0, pb1;
        if (notlast) {
            pa0 = *(const float4*)(Aptr + k0 + 16);
            pa1 = *(const float4*)(Aptr + k0 + 20);
            pb0 = *(const float4*)(Bptr + k0 + 16);
            pb1 = *(const float4*)(Bptr + k0 + 20);
        }

#pragma unroll
        for (int kk = 0; kk < 16; kk += 8) {
            unsigned ah[2][4], al[2][4];
#pragma unroll
            for (int mi = 0; mi < 2; mi++) {
                split_tf32(As[buf][kk + t4][wm + mi * 16 + g],     ah[mi][0], al[mi][0]);
                split_tf32(As[buf][kk + t4][wm + mi * 16 + g + 8], ah[mi][1], al[mi][1]);
                split_tf32(As[buf][kk + t4 + 4][wm + mi * 16 + g],     ah[mi][2], al[mi][2]);
                split_tf32(As[buf][kk + t4 + 4][wm + mi * 16 + g + 8], ah[mi][3], al[mi][3]);
            }
            unsigned bh[4][2], bl[4][2];
#pragma unroll
            for (int ni = 0; ni < 4; ni++) {
                split_tf32(Bs[buf][kk + t4][wn + ni * 8 + g],     bh[ni][0], bl[ni][0]);
                split_tf32(Bs[buf][kk + t4 + 4][wn + ni * 8 + g], bh[ni][1], bl[ni][1]);
            }
#pragma unroll
            for (int mi = 0; mi < 2; mi++)
#pragma unroll
                for (int ni = 0; ni < 4; ni++) {
                    float* c = acc[mi][ni];
                    mma8(c, al[mi][0], al[mi][1], al[mi][2], al[mi][3], bh[ni][0], bh[ni][1]);
                    mma8(c, ah[mi][0], ah[mi][1], ah[mi][2], ah[mi][3], bl[ni][0], bl[ni][1]);
                    mma8(c, ah[mi][0], ah[mi][1], ah[mi][2], ah[mi][3], bh[ni][0], bh[ni][1]);
                }
        }

        if (notlast) {
            int nb = buf ^ 1;
            As[nb][ak + 0][arow] = pa0.x; As[nb][ak + 1][arow] = pa0.y;
            As[nb][ak + 2][arow] = pa0.z; As[nb][ak + 3][arow] = pa0.w;
            As[nb][ak + 4][arow] = pa1.x; As[nb][ak + 5][arow] = pa1.y;
            As[nb][ak + 6][arow] = pa1.z; As[nb][ak + 7][arow] = pa1.w;
            Bs[nb][ak + 0][arow] = pb0.x; Bs[nb][ak + 1][arow] = pb0.y;
            Bs[nb][ak + 2][arow] = pb0.z; Bs[nb][ak + 3][arow] = pb0.w;
            Bs[nb][ak + 4][arow] = pb1.x; Bs[nb][ak + 5][arow] = pb1.y;
            Bs[nb][ak + 6][arow] = pb1.z; Bs[nb][ak + 7][arow] = pb1.w;
            __syncthreads();
            buf = nb;
        }
    }

#pragma unroll
    for (int mi = 0; mi < 2; mi++) {
        int r0 = m0 + wm + mi * 16 + g;
        int r1 = r0 + 8;
        const float* t0 = nullptr;
        const float* t1 = nullptr;
        if (EP == 2) {
            t0 = temb + (size_t)labels[r0] * 256;
            t1 = temb + (size_t)labels[r1] * 256;
        }
#pragma unroll
        for (int ni = 0; ni < 4; ni++) {
            int c0 = n0 + wn + ni * 8 + (t4 << 1);
            float v00 = acc[mi][ni][0], v01 = acc[mi][ni][1];
            float v10 = acc[mi][ni][2], v11 = acc[mi][ni][3];
            float bx = bias[c0], by = bias[c0 + 1];
            v00 += bx; v01 += by; v10 += bx; v11 += by;
            if (EP == 1) {
                v00 = gelu_f(v00); v01 = gelu_f(v01);
                v10 = gelu_f(v10); v11 = gelu_f(v11);
            }
            if (EP == 2) {
                v00 += t0[c0]; v01 += t0[c0 + 1];
                v10 += t1[c0]; v11 += t1[c0 + 1];
            }
            if (EP == 4 && blockIdx.z < 2) {
                const int z = blockIdx.z;
                unsigned h0, l0, h1, l1;
                packsplit(v00, v01, h0, l0);
                packsplit(v10, v11, h1, l1);
                size_t i0 = ((size_t)z * PTS + r0) * 128 + (c0 >> 1);
                size_t i1 = ((size_t)z * PTS + r1) * 128 + (c0 >> 1);
                uh[i0] = h0; ul[i0] = l0;
                uh[i1] = h1; ul[i1] = l1;
            } else {
                *(float2*)(C + (size_t)r0 * ldc + c0) = make_float2(v00, v01);
                *(float2*)(C + (size_t)r1 * ldc + c0) = make_float2(v10, v11);
            }
        }
    }
}

// ---------------- fused attention: packed bf16 QK + tf32x3 PV ---------------
// grid (8 q-tiles, 4 heads, 8 batch), 128 threads.
__global__ void __launch_bounds__(128) attn_fused(const unsigned* __restrict__ QKh,
                                                  const unsigned* __restrict__ QKl,
                                                  const float* __restrict__ V,
                                                  float* __restrict__ O) {
    __shared__ unsigned Qh[32][72], Ql[32][72];   // [d2][qrow]
    __shared__ unsigned Kh[32][40], Kl[32][40];   // [d2][kpos]
    __shared__ __align__(16) float Vs[32][68];    // [kpos][d]
    __shared__ float Ss[64][36];                  // [q][kpos]
    __shared__ float rm[64], rl[64], rf[64];

    const int b = blockIdx.z, h = blockIdx.y, q0 = blockIdx.x << 6;
    const int tid = threadIdx.x;
    const int lane = tid & 31, wid = tid >> 5;
    const int g = lane >> 2, t4 = lane & 3;

    const unsigned* Qgh = QKh + ((size_t)(b * 512 + q0)) * 128 + h * 32;
    const unsigned* Qgl = QKl + ((size_t)(b * 512 + q0)) * 128 + h * 32;
    const unsigned* Kgh = QKh + (size_t)PTS * 128 + ((size_t)b * 512) * 128 + h * 32;
    const unsigned* Kgl = QKl + (size_t)PTS * 128 + ((size_t)b * 512) * 128 + h * 32;
    const float* Vg = V + ((size_t)b * 512) * 256 + h * 64;

    {   // stage Q tile: [d2][qrow]
        int qrow = tid >> 1, half = (tid & 1) << 4;
        const uint4* sh = (const uint4*)(Qgh + (size_t)qrow * 128 + half);
        const uint4* sl = (const uint4*)(Qgl + (size_t)qrow * 128 + half);
#pragma unroll
        for (int j = 0; j < 4; j++) {
            uint4 vh = sh[j], vl = sl[j];
            int d2 = half + j * 4;
            Qh[d2 + 0][qrow] = vh.x; Ql[d2 + 0][qrow] = vl.x;
            Qh[d2 + 1][qrow] = vh.y; Ql[d2 + 1][qrow] = vl.y;
            Qh[d2 + 2][qrow] = vh.z; Ql[d2 + 2][qrow] = vl.z;
            Qh[d2 + 3][qrow] = vh.w; Ql[d2 + 3][qrow] = vl.w;
        }
    }
    if (tid < 64) { rm[tid] = -1e30f; rl[tid] = 0.0f; }

    const int wm = (wid >> 1) << 5, wn = (wid & 1) << 5;
    const int sm = wid << 4;     // S-phase: warp owns 16 q-rows
    float oacc[2][4][4] = {};

    for (int kc = 0; kc < 512; kc += 32) {
        __syncthreads();
        {   // stage K packed [d2][kpos]
            int kpos = tid >> 2, seg = (tid & 3) << 3;
            const uint4* sh = (const uint4*)(Kgh + (size_t)(kc + kpos) * 128 + seg);
            const uint4* sl = (const uint4*)(Kgl + (size_t)(kc + kpos) * 128 + seg);
#pragma unroll
            for (int j = 0; j < 2; j++) {
                uint4 vh = sh[j], vl = sl[j];
                int d2 = seg + j * 4;
                Kh[d2 + 0][kpos] = vh.x; Kl[d2 + 0][kpos] = vl.x;
                Kh[d2 + 1][kpos] = vh.y; Kl[d2 + 1][kpos] = vl.y;
                Kh[d2 + 2][kpos] = vh.z; Kl[d2 + 2][kpos] = vl.z;
                Kh[d2 + 3][kpos] = vh.w; Kl[d2 + 3][kpos] = vl.w;
            }
        }
        {   // stage V floats [kpos][d]
            int i = tid >> 2, d0 = (tid & 3) << 4;
            const float* vsrc = Vg + (size_t)(kc + i) * 256 + d0;
#pragma unroll
            for (int j = 0; j < 4; j++)
                *(float4*)&Vs[i][d0 + j * 4] = *(const float4*)(vsrc + j * 4);
        }
        __syncthreads();

        // S = Q K^T (packed bf16 x3): warp computes 16 rows x 32 cols
        float sacc[4][4] = {};
#pragma unroll
        for (int kk2 = 0; kk2 < 32; kk2 += 8) {
            int r0 = sm + g, r1 = r0 + 8;
            unsigned a0h = Qh[kk2 + t4][r0],     a0l = Ql[kk2 + t4][r0];
            unsigned a1h = Qh[kk2 + t4][r1],     a1l = Ql[kk2 + t4][r1];
            unsigned a2h = Qh[kk2 + t4 + 4][r0], a2l = Ql[kk2 + t4 + 4][r0];
            unsigned a3h = Qh[kk2 + t4 + 4][r1], a3l = Ql[kk2 + t4 + 4][r1];
#pragma unroll
            for (int ni = 0; ni < 4; ni++) {
                int c = ni * 8 + g;
                unsigned b0h = Kh[kk2 + t4][c],     b0l = Kl[kk2 + t4][c];
                unsigned b1h = Kh[kk2 + t4 + 4][c], b1l = Kl[kk2 + t4 + 4][c];
                mma16(sacc[ni], a0l, a1l, a2l, a3l, b0h, b1h);
                mma16(sacc[ni], a0h, a1h, a2h, a3h, b0l, b1l);
                mma16(sacc[ni], a0h, a1h, a2h, a3h, b0h, b1h);
            }
        }
#pragma unroll
        for (int ni = 0; ni < 4; ni++) {
            int c = (ni << 3) + (t4 << 1);
            Ss[sm + g][c]         = sacc[ni][0] * 0.125f;
            Ss[sm + g][c + 1]     = sacc[ni][1] * 0.125f;
            Ss[sm + g + 8][c]     = sacc[ni][2] * 0.125f;
            Ss[sm + g + 8][c + 1] = sacc[ni][3] * 0.125f;
        }
        __syncthreads();

        // online softmax update (thread t handles row t)
        if (tid < 64) {
            float mold = rm[tid];
            float mx = mold;
#pragma unroll
            for (int j = 0; j < 32; j++) mx = fmaxf(mx, Ss[tid][j]);
            float f = __expf(mold - mx);
            float sum = 0.0f;
#pragma unroll
            for (int j = 0; j < 32; j++) {
                float p = __expf(Ss[tid][j] - mx);
                Ss[tid][j] = p;
                sum += p;
            }
            rl[tid] = rl[tid] * f + sum;
            rm[tid] = mx;
            rf[tid] = f;
        }
        __syncthreads();

        // rescale accumulators, then O += P V (tf32 x3)
#pragma unroll
        for (int mi = 0; mi < 2; mi++) {
            float f0 = rf[wm + (mi << 4) + g];
            float f1 = rf[wm + (mi << 4) + g + 8];
#pragma unroll
            for (int ni = 0; ni < 4; ni++) {
                oacc[mi][ni][0] *= f0; oacc[mi][ni][1] *= f0;
                oacc[mi][ni][2] *= f1; oacc[mi][ni][3] *= f1;
            }
        }
#pragma unroll
        for (int kk = 0; kk < 32; kk += 8) {
            unsigned ah[2][4], al[2][4];
#pragma unroll
            for (int mi = 0; mi < 2; mi++) {
                split_tf32(Ss[wm + (mi << 4) + g][kk + t4],         ah[mi][0], al[mi][0]);
                split_tf32(Ss[wm + (mi << 4) + g + 8][kk + t4],     ah[mi][1], al[mi][1]);
                split_tf32(Ss[wm + (mi << 4) + g][kk + t4 + 4],     ah[mi][2], al[mi][2]);
                split_tf32(Ss[wm + (mi << 4) + g + 8][kk + t4 + 4], ah[mi][3], al[mi][3]);
            }
#pragma unroll
            for (int ni = 0; ni < 4; ni++) {
                unsigned bh0, bh1, bl0, bl1;
                split_tf32(Vs[kk + t4][wn + ni * 8 + g],     bh0, bl0);
                split_tf32(Vs[kk + t4 + 4][wn + ni * 8 + g], bh1, bl1);
#pragma unroll
                for (int mi = 0; mi < 2; mi++) {
                    float* c = oacc[mi][ni];
                    mma8(c, al[mi][0], al[mi][1], al[mi][2], al[mi][3], bh0, bh1);
                    mma8(c, ah[mi][0], ah[mi][1], ah[mi][2], ah[mi][3], bl0, bl1);
                    mma8(c, ah[mi][0], ah[mi][1], ah[mi][2], ah[mi][3], bh0, bh1);
                }
            }
        }
    }

    float* Og = O + ((size_t)(b * 512 + q0)) * 256 + h * 64;
#pragma unroll
    for (int mi = 0; mi < 2; mi++) {
        int r0 = wm + (mi << 4) + g, r1 = r0 + 8;
        float il0 = 1.0f / rl[r0], il1 = 1.0f / rl[r1];
#pragma unroll
        for (int ni = 0; ni < 4; ni++) {
            int c = wn + (ni << 3) + (t4 << 1);
            *(float2*)(Og + (size_t)r0 * 256 + c) =
                make_float2(oacc[mi][ni][0] * il0, oacc[mi][ni][1] * il0);
            *(float2*)(Og + (size_t)r1 * 256 + c) =
                make_float2(oacc[mi][ni][2] * il1, oacc[mi][ni][3] * il1);
        }
    }
}

// ---------------- layer norm: warp per row ----------------------------------
template <int WIDTH, bool GELU, bool RES>
__global__ void __launch_bounds__(128) ln_warp(const float* __restrict__ in,
                                               const float* __restrict__ res,
                                               const float* __restrict__ g,
                                               const float* __restrict__ bv,
                                               float* __restrict__ out) {
    const int V4 = WIDTH / 128;
    int w = threadIdx.x >> 5, lane = threadIdx.x & 31;
    int row = (blockIdx.x << 2) + w;
    const float4* ip = (const float4*)(in + (size_t)row * WIDTH);
    const float4* rp = (const float4*)(res + (size_t)row * WIDTH);
    float4 v[V4];
    float s = 0.0f;
#pragma unroll
    for (int i = 0; i < V4; i++) {
        v[i] = ip[lane + 32 * i];
        if (RES) {
            float4 r = rp[lane + 32 * i];
            v[i].x += r.x; v[i].y += r.y; v[i].z += r.z; v[i].w += r.w;
        }
        s += v[i].x + v[i].y + v[i].z + v[i].w;
    }
#pragma unroll
    for (int o = 16; o; o >>= 1) s += __shfl_xor_sync(0xffffffffu, s, o);
    float mean = s * (1.0f / WIDTH);
    float q = 0.0f;
#pragma unroll
    for (int i = 0; i < V4; i++) {
        v[i].x -= mean; v[i].y -= mean; v[i].z -= mean; v[i].w -= mean;
        q += v[i].x * v[i].x + v[i].y * v[i].y + v[i].z * v[i].z + v[i].w * v[i].w;
    }
#pragma unroll
    for (int o = 16; o; o >>= 1) q += __shfl_xor_sync(0xffffffffu, q, o);
    float inv = rsqrtf(q * (1.0f / WIDTH) + 1e-5f);
    const float4* gp = (const float4*)g;
    const float4* bp = (const float4*)bv;
    float4* op = (float4*)(out + (size_t)row * WIDTH);
#pragma unroll
    for (int i = 0; i < V4; i++) {
        float4 gg = gp[lane + 32 * i], bb = bp[lane + 32 * i];
        float4 o;
        o.x = gg.x * v[i].x * inv + bb.x;
        o.y = gg.y * v[i].y * inv + bb.y;
        o.z = gg.z * v[i].z * inv + bb.z;
        o.w = gg.w * v[i].w * inv + bb.w;
        if (GELU) {
            o.x = gelu_f(o.x); o.y = gelu_f(o.y);
            o.z = gelu_f(o.z); o.w = gelu_f(o.w);
        }
        op[lane + 32 * i] = o;
    }
}

// ---------------- launch ----------------------------------------------------
extern "C" void kernel_launch(void* const* d_in, const int* in_sizes, int n_in,
                              void* d_out, int out_size) {
    (void)in_sizes; (void)n_in; (void)out_size;
    const float* image  = (const float*)d_in[0];
    const float* coords = (const float*)d_in[1];
    const int*   labels = (const int*)d_in[2];
    const float* pe_w   = (const float*)d_in[3];
    const float* pe_b   = (const float*)d_in[4];
    const float* temb   = (const float*)d_in[5];
    const float* fbi    = (const float*)d_in[6];
    const float* fe1_w  = (const float*)d_in[7];
    const float* fe1_b  = (const float*)d_in[8];
    const float* feln1g = (const float*)d_in[9];
    const float* feln1b = (const float*)d_in[10];
    const float* fe2_w  = (const float*)d_in[11];
    const float* fe2_b  = (const float*)d_in[12];
    const float* feln2g = (const float*)d_in[13];
    const float* feln2b = (const float*)d_in[14];
    const float* in_w   = (const float*)d_in[15];
    const float* in_b   = (const float*)d_in[16];
    const float* ao_w   = (const float*)d_in[17];
    const float* ao_b   = (const float*)d_in[18];
    const float* n1_g   = (const float*)d_in[19];
    const float* n1_b   = (const float*)d_in[20];
    const float* f1_w   = (const float*)d_in[21];
    const float* f1_b   = (const float*)d_in[22];
    const float* f2_w   = (const float*)d_in[23];
    const float* f2_b   = (const float*)d_in[24];
    const float* n2_g   = (const float*)d_in[25];
    const float* n2_b   = (const float*)d_in[26];
    const float* op_w   = (const float*)d_in[27];
    const float* op_b   = (const float*)d_in[28];
    float* out = (float*)d_out;

    float *p_pe, *p_spatial, *p_feat, *p_fe1, *p_h1, *p_fe2, *p_freq;
    float *p_v, *p_o, *p_ao, *p_x, *p_ffh, *p_ff2, *p_x2;
    unsigned *p_qkh, *p_qkl;
    cudaGetSymbolAddress((void**)&p_pe, g_pe);
    cudaGetSymbolAddress((void**)&p_spatial, g_spatial);
    cudaGetSymbolAddress((void**)&p_feat, g_feat);
    cudaGetSymbolAddress((void**)&p_fe1, g_fe1);
    cudaGetSymbolAddress((void**)&p_h1, g_h1);
    cudaGetSymbolAddress((void**)&p_fe2, g_fe2);
    cudaGetSymbolAddress((void**)&p_freq, g_freq);
    cudaGetSymbolAddress((void**)&p_qkh, g_qkh);
    cudaGetSymbolAddress((void**)&p_qkl, g_qkl);
    cudaGetSymbolAddress((void**)&p_v, g_v);
    cudaGetSymbolAddress((void**)&p_o, g_o);
    cudaGetSymbolAddress((void**)&p_ao, g_ao);
    cudaGetSymbolAddress((void**)&p_x, g_x);
    cudaGetSymbolAddress((void**)&p_ffh, g_ffh);
    cudaGetSymbolAddress((void**)&p_ff2, g_ff2);
    cudaGetSymbolAddress((void**)&p_x2, g_x2);

    // 1) sinusoidal PE
    pe_kernel<<<PTS, 128>>>(coords, p_pe);
    // 2) spatial = PE @ pe_w^T + pe_b + type_emb[label]
    gemm_tc<2><<<dim3(4, 64, 1), 128>>>(p_pe, pe_w, pe_b, p_spatial,
        256, 256, 256, 256, labels, temb, nullptr, nullptr, nullptr);
    // 3) patch FFT features
    fft_feat_kernel<<<PTS, 256>>>(image, coords, fbi, p_feat);
    // 4) freq MLP
    gemm_tc<0><<<dim3(2, 64, 1), 128>>>(p_feat, fe1_w, fe1_b, p_fe1,
        16, 16, 16, 128, nullptr, nullptr, nullptr, nullptr, nullptr);
    ln_warp<128, true, false><<<PTS / 4, 128>>>(p_fe1, p_fe1, feln1g, feln1b, p_h1);
    gemm_tc<0><<<dim3(4, 64, 1), 128>>>(p_h1, fe2_w, fe2_b, p_fe2,
        128, 128, 128, 256, nullptr, nullptr, nullptr, nullptr, nullptr);
    ln_warp<256, false, false><<<PTS / 4, 128>>>(p_fe2, p_fe2, feln2g, feln2b, p_freq);
    // 5) fused Q/K/V projections: z=0,1 -> packed bf16 Q/K; z=2 -> float V
    gemm_tc<4><<<dim3(4, 64, 3), 128>>>(p_spatial, in_w, in_b, p_v,
        256, 256, 256, 256, nullptr, nullptr, p_freq, p_qkh, p_qkl);
    // 6) fused attention
    attn_fused<<<dim3(8, 4, 8), 128>>>(p_qkh, p_qkl, p_v, p_o);
    // 7) attn out proj + residual LN
    gemm_tc<0><<<dim3(4, 64, 1), 128>>>(p_o, ao_w, ao_b, p_ao,
        256, 256, 256, 256, nullptr, nullptr, nullptr, nullptr, nullptr);
    ln_warp<256, false, true><<<PTS / 4, 128>>>(p_ao, p_spatial, n1_g, n1_b, p_x);
    // 8) FFN
    gemm_tc<1><<<dim3(8, 64, 1), 128>>>(p_x, f1_w, f1_b, p_ffh,
        256, 256, 256, 512, nullptr, nullptr, nullptr, nullptr, nullptr);
    gemm_tc<0><<<dim3(4, 64, 1), 128>>>(p_ffh, f2_w, f2_b, p_ff2,
        512, 512, 512, 256, nullptr, nullptr, nullptr, nullptr, nullptr);
    ln_warp<256, false, true><<<PTS / 4, 128>>>(p_ff2, p_x, n2_g, n2_b, p_x2);
    // 9) output projection
    gemm_tc<0><<<dim3(4, 64, 1), 128>>>(p_x2, op_w, op_b, out,
        256, 256, 256, 256, nullptr, nullptr, nullptr, nullptr, nullptr);
}

// round 10
// speedup vs baseline: 1.3144x; 1.0143x over previous
#include <cuda_runtime.h>
#include <math.h>

#define PTS 4096      // B*N = 8*512

// ---------------- scratch (device globals) ----------------------------------
__device__ float g_pe[PTS * 256];
__device__ float g_spatial[PTS * 256];
__device__ float g_feat[PTS * 16];
__device__ float g_h1[PTS * 128];
__device__ float g_freq[PTS * 256];
__device__ unsigned g_qkh[2u * PTS * 128];  // packed bf16 hi: Q | K (d-pairs)
__device__ unsigned g_qkl[2u * PTS * 128];  // packed bf16 lo
__device__ float g_v[PTS * 256];
__device__ float g_o[PTS * 256];
__device__ float g_x[PTS * 256];
__device__ float g_ffh[PTS * 512];
__device__ float g_x2[PTS * 256];

__device__ __forceinline__ float gelu_f(float x) {
    return 0.5f * x * (1.0f + erff(x * 0.7071067811865475f));
}

// tf32 helpers ---------------------------------------------------------------
__device__ __forceinline__ unsigned tf32_rna(float x) {
    unsigned r;
    asm("cvt.rna.tf32.f32 %0, %1;" : "=r"(r) : "f"(x));
    return r;
}
__device__ __forceinline__ void mma8(float* c, unsigned a0, unsigned a1,
                                     unsigned a2, unsigned a3,
                                     unsigned b0, unsigned b1) {
    asm("mma.sync.aligned.m16n8k8.row.col.f32.tf32.tf32.f32 "
        "{%0,%1,%2,%3},{%4,%5,%6,%7},{%8,%9},{%0,%1,%2,%3};"
        : "+f"(c[0]), "+f"(c[1]), "+f"(c[2]), "+f"(c[3])
        : "r"(a0), "r"(a1), "r"(a2), "r"(a3), "r"(b0), "r"(b1));
}
__device__ __forceinline__ void split_tf32(float x, unsigned& hi, unsigned& lo) {
    hi = tf32_rna(x);
    lo = __float_as_uint(x - __uint_as_float(hi));
}

// bf16x2 helpers --------------------------------------------------------------
__device__ __forceinline__ void packsplit(float x0, float x1,
                                          unsigned& h, unsigned& l) {
    unsigned hh;
    asm("cvt.rn.bf16x2.f32 %0, %1, %2;" : "=r"(hh) : "f"(x1), "f"(x0));
    float r0 = x0 - __uint_as_float(hh << 16);
    float r1 = x1 - __uint_as_float(hh & 0xffff0000u);
    asm("cvt.rn.bf16x2.f32 %0, %1, %2;" : "=r"(l) : "f"(r1), "f"(r0));
    h = hh;
}
__device__ __forceinline__ void mma16(float* c,
                                      unsigned a0, unsigned a1, unsigned a2, unsigned a3,
                                      unsigned b0, unsigned b1) {
    asm("mma.sync.aligned.m16n8k16.row.col.f32.bf16.bf16.f32 "
        "{%0,%1,%2,%3},{%4,%5,%6,%7},{%8,%9},{%0,%1,%2,%3};"
        : "+f"(c[0]), "+f"(c[1]), "+f"(c[2]), "+f"(c[3])
        : "r"(a0), "r"(a1), "r"(a2), "r"(a3), "r"(b0), "r"(b1));
}

// ---------------- PE kernel -------------------------------------------------
__global__ void __launch_bounds__(128) pe_kernel(const float* __restrict__ coords,
                                                 float* __restrict__ pe) {
    int pt = blockIdx.x, t = threadIdx.x;
    int i = t & 63, comp = t >> 6;
    float c = coords[pt * 2 + comp] * (1.0f / 1024.0f);
    float arg = c * 6.283185307179586f * exp2f(-(float)i * 0.4152410118609203f);
    float s, co;
    sincosf(arg, &s, &co);
    size_t base = (size_t)pt * 256 + (comp << 7) + i;
    pe[base] = s;
    pe[base + 64] = co;
}

// ---------------- patch gather + 2D DFT + radial binning --------------------
__global__ void __launch_bounds__(256) fft_feat_kernel(const float* __restrict__ image,
                                                       const float* __restrict__ coords,
                                                       const float* __restrict__ fbi,
                                                       float* __restrict__ feat) {
    int pt = blockIdx.x;
    int b = pt >> 9;
    int tid = threadIdx.x;

    __shared__ float patch[16][16];
    __shared__ float Rre[16][9], Rim[16][9];
    __shared__ float twc[16], tws[16];
    __shared__ float bmag[8], bang[8];
    __shared__ int bcnt[8];
    __shared__ float smf[8];
    __shared__ int spx, spy;

    if (tid == 0) {
        float cx = coords[pt * 2];
        float cy = coords[pt * 2 + 1];
        int px = (int)cx; px = min(max(px, 8), 1015);
        int py = (int)cy; py = min(max(py, 8), 1015);
        spx = px; spy = py;
        float mx = -1e30f;
        for (int i = 0; i < 8; i++) mx = fmaxf(mx, fbi[i]);
        float s = 0.0f;
        for (int i = 0; i < 8; i++) { float e = expf(fbi[i] - mx); smf[i] = e; s += e; }
        float inv = 1.0f / s;
        for (int i = 0; i < 8; i++) smf[i] *= inv;
    }
    if (tid < 16) {
        twc[tid] = cospif((float)tid / 8.0f);
        tws[tid] = sinpif(-(float)tid / 8.0f);
    }
    if (tid < 8) { bmag[tid] = 0.0f; bang[tid] = 0.0f; bcnt[tid] = 0; }
    __syncthreads();

    int y = tid >> 4, x = tid & 15;
    int yy = spy - 8 + y, xx = spx - 8 + x;
    const float* imb = image + (size_t)b * 3u * 1024u * 1024u;
    size_t off = (size_t)yy * 1024 + xx;
    float gsum = imb[off] + imb[1048576u + off] + imb[2097152u + off];
    patch[y][x] = gsum * (1.0f / 3.0f);
    __syncthreads();

    if (tid < 144) {
        int ry = tid / 9, kx = tid % 9;
        float re = 0.0f, im = 0.0f;
#pragma unroll
        for (int j = 0; j < 16; j++) {
            float pv = patch[ry][j];
            int t = (kx * j) & 15;
            re += pv * twc[t];
            im += pv * tws[t];
        }
        Rre[ry][kx] = re;
        Rim[ry][kx] = im;
    }
    __syncthreads();

    if (tid < 144) {
        int ky = tid / 9, kx = tid % 9;
        float re = 0.0f, im = 0.0f;
#pragma unroll
        for (int j = 0; j < 16; j++) {
            int t = (ky * j) & 15;
            float c = twc[t], s = tws[t];
            float ar = Rre[j][kx], ai = Rim[j][kx];
            re += ar * c - ai * s;
            im += ar * s + ai * c;
        }
        re *= 0.0625f;
        im *= 0.0625f;
        float mag = sqrtf(re * re + im * im);
        float ang = atan2f(im, re);

        double fy = (ky < 8) ? (double)ky / 16.0 : ((double)ky - 16.0) / 16.0;
        double fx = (double)kx / 16.0;
        double r = sqrt(fx * fx + fy * fy);
        double maxr = 0.7071067811865476 + 1e-6;
        double step = maxr / 8.0;
        int bi = 0;
#pragma unroll
        for (int k = 1; k < 9; k++) if (r >= (double)k * step) bi = k;
        if (bi > 7) bi = 7;
        atomicAdd(&bmag[bi], mag);
        atomicAdd(&bang[bi], ang);
        atomicAdd(&bcnt[bi], 1);
    }
    __syncthreads();

    if (tid < 8) {
        float c = (float)max(bcnt[tid], 1);
        feat[(size_t)pt * 16 + tid]     = bmag[tid] / c * smf[tid];
        feat[(size_t)pt * 16 + 8 + tid] = bang[tid] / c;
    }
}

// ---------------- tensor-core GEMM (tf32 x3): C = A @ B^T + bias ------------
// 64x64 tile, 128 threads (2x2 warp tiles of 32x32), double-buffered.
// EP: 0 bias, 1 bias+gelu, 2 bias+type_emb, 4 QKV (z<2 packed bf16 out, z=2 float).
template <int EP>
__global__ void __launch_bounds__(128) gemm_tc(
    const float* __restrict__ A, const float* __restrict__ B,
    const float* __restrict__ bias, float* __restrict__ C,
    int K, int lda, int ldb, int ldc,
    const int* __restrict__ labels, const float* __restrict__ temb,
    const float* __restrict__ A2,
    unsigned* __restrict__ uh, unsigned* __restrict__ ul)
{
    __shared__ __align__(16) float As[2][16][72];
    __shared__ __align__(16) float Bs[2][16][72];

    if (EP == 4) {
        const int z = blockIdx.z;
        if (z > 0) A = A2;
        B += (size_t)z * 65536;
        bias += z << 8;
    }

    const int tid = threadIdx.x;
    const int m0 = blockIdx.y << 6, n0 = blockIdx.x << 6;

    const int arow = tid >> 1, ak = (tid & 1) << 3;
    const float* Aptr = A + (size_t)(m0 + arow) * lda + ak;
    const float* Bptr = B + (size_t)(n0 + arow) * ldb + ak;

    const int lane = tid & 31, wid = tid >> 5;
    const int g = lane >> 2, t4 = lane & 3;
    const int wm = (wid >> 1) << 5;
    const int wn = (wid & 1) << 5;

    float acc[2][4][4] = {};

    {
        float4 a0 = *(const float4*)Aptr;
        float4 a1 = *(const float4*)(Aptr + 4);
        As[0][ak + 0][arow] = a0.x; As[0][ak + 1][arow] = a0.y;
        As[0][ak + 2][arow] = a0.z; As[0][ak + 3][arow] = a0.w;
        As[0][ak + 4][arow] = a1.x; As[0][ak + 5][arow] = a1.y;
        As[0][ak + 6][arow] = a1.z; As[0][ak + 7][arow] = a1.w;
        float4 b0 = *(const float4*)Bptr;
        float4 b1 = *(const float4*)(Bptr + 4);
        Bs[0][ak + 0][arow] = b0.x; Bs[0][ak + 1][arow] = b0.y;
        Bs[0][ak + 2][arow] = b0.z; Bs[0][ak + 3][arow] = b0.w;
        Bs[0][ak + 4][arow] = b1.x; Bs[0][ak + 5][arow] = b1.y;
        Bs[0][ak + 6][arow] = b1.z; Bs[0][ak + 7][arow] = b1.w;
    }
    __syncthreads();

    int buf = 0;
    for (int k0 = 0; k0 < K; k0 += 16) {
        const bool notlast = (k0 + 16 < K);
        float4 pa0, pa1, pb0, pb1;
        if (notlast) {
            pa0 = *(const float4*)(Aptr + k0 + 16);
            pa1 = *(const float4*)(Aptr + k0 + 20);
            pb0 = *(const float4*)(Bptr + k0 + 16);
            pb1 = *(const float4*)(Bptr + k0 + 20);
        }

#pragma unroll
        for (int kk = 0; kk < 16; kk += 8) {
            unsigned ah[2][4], al[2][4];
#pragma unroll
            for (int mi = 0; mi < 2; mi++) {
                split_tf32(As[buf][kk + t4][wm + mi * 16 + g],     ah[mi][0], al[mi][0]);
                split_tf32(As[buf][kk + t4][wm + mi * 16 + g + 8], ah[mi][1], al[mi][1]);
                split_tf32(As[buf][kk + t4 + 4][wm + mi * 16 + g],     ah[mi][2], al[mi][2]);
                split_tf32(As[buf][kk + t4 + 4][wm + mi * 16 + g + 8], ah[mi][3], al[mi][3]);
            }
            unsigned bh[4][2], bl[4][2];
#pragma unroll
            for (int ni = 0; ni < 4; ni++) {
                split_tf32(Bs[buf][kk + t4][wn + ni * 8 + g],     bh[ni][0], bl[ni][0]);
                split_tf32(Bs[buf][kk + t4 + 4][wn + ni * 8 + g], bh[ni][1], bl[ni][1]);
            }
#pragma unroll
            for (int mi = 0; mi < 2; mi++)
#pragma unroll
                for (int ni = 0; ni < 4; ni++) {
                    float* c = acc[mi][ni];
                    mma8(c, al[mi][0], al[mi][1], al[mi][2], al[mi][3], bh[ni][0], bh[ni][1]);
                    mma8(c, ah[mi][0], ah[mi][1], ah[mi][2], ah[mi][3], bl[ni][0], bl[ni][1]);
                    mma8(c, ah[mi][0], ah[mi][1], ah[mi][2], ah[mi][3], bh[ni][0], bh[ni][1]);
                }
        }

        if (notlast) {
            int nb = buf ^ 1;
            As[nb][ak + 0][arow] = pa0.x; As[nb][ak + 1][arow] = pa0.y;
            As[nb][ak + 2][arow] = pa0.z; As[nb][ak + 3][arow] = pa0.w;
            As[nb][ak + 4][arow] = pa1.x; As[nb][ak + 5][arow] = pa1.y;
            As[nb][ak + 6][arow] = pa1.z; As[nb][ak + 7][arow] = pa1.w;
            Bs[nb][ak + 0][arow] = pb0.x; Bs[nb][ak + 1][arow] = pb0.y;
            Bs[nb][ak + 2][arow] = pb0.z; Bs[nb][ak + 3][arow] = pb0.w;
            Bs[nb][ak + 4][arow] = pb1.x; Bs[nb][ak + 5][arow] = pb1.y;
            Bs[nb][ak + 6][arow] = pb1.z; Bs[nb][ak + 7][arow] = pb1.w;
            __syncthreads();
            buf = nb;
        }
    }

#pragma unroll
    for (int mi = 0; mi < 2; mi++) {
        int r0 = m0 + wm + mi * 16 + g;
        int r1 = r0 + 8;
        const float* t0 = nullptr;
        const float* t1 = nullptr;
        if (EP == 2) {
            t0 = temb + (size_t)labels[r0] * 256;
            t1 = temb + (size_t)labels[r1] * 256;
        }
#pragma unroll
        for (int ni = 0; ni < 4; ni++) {
            int c0 = n0 + wn + ni * 8 + (t4 << 1);
            float v00 = acc[mi][ni][0], v01 = acc[mi][ni][1];
            float v10 = acc[mi][ni][2], v11 = acc[mi][ni][3];
            float bx = bias[c0], by = bias[c0 + 1];
            v00 += bx; v01 += by; v10 += bx; v11 += by;
            if (EP == 1) {
                v00 = gelu_f(v00); v01 = gelu_f(v01);
                v10 = gelu_f(v10); v11 = gelu_f(v11);
            }
            if (EP == 2) {
                v00 += t0[c0]; v01 += t0[c0 + 1];
                v10 += t1[c0]; v11 += t1[c0 + 1];
            }
            if (EP == 4 && blockIdx.z < 2) {
                const int z = blockIdx.z;
                unsigned h0, l0, h1, l1;
                packsplit(v00, v01, h0, l0);
                packsplit(v10, v11, h1, l1);
                size_t i0 = ((size_t)z * PTS + r0) * 128 + (c0 >> 1);
                size_t i1 = ((size_t)z * PTS + r1) * 128 + (c0 >> 1);
                uh[i0] = h0; ul[i0] = l0;
                uh[i1] = h1; ul[i1] = l1;
            } else {
                *(float2*)(C + (size_t)r0 * ldc + c0) = make_float2(v00, v01);
                *(float2*)(C + (size_t)r1 * ldc + c0) = make_float2(v10, v11);
            }
        }
    }
}

// ---------------- GEMM + fused LayerNorm: 32 x W tile (full rows) -----------
// C = LN( A @ B^T + bias (+ res) ) [then gelu if GELU_AFTER]; W = 128 or 256.
// 128 threads; 4 warps each own 32 rows x (W/4) cols.
template <int W, bool RES, bool GELU_AFTER>
__global__ void __launch_bounds__(128) gemm_ln(
    const float* __restrict__ A, const float* __restrict__ Bw,
    const float* __restrict__ bias, const float* __restrict__ res,
    const float* __restrict__ gam, const float* __restrict__ bet,
    float* __restrict__ C, int K, int lda)
{
    constexpr int NI = W / 32;           // n8-tiles per warp
    __shared__ __align__(16) float As[2][16][36];
    __shared__ __align__(16) float Bs[2][16][W + 8];
    __shared__ float rsum[32][4], rsq[32][4];
    __shared__ float smean[32], sistd[32];

    const int tid = threadIdx.x;
    const int m0 = blockIdx.x << 5;

    // A staging: 32 rows x 16 k, one float4/thread
    const int arow = tid >> 2, ak4 = (tid & 3) << 2;
    const float* Aptr = A + (size_t)(m0 + arow) * lda + ak4;
    // B staging: W rows x 16 k, (W/64) float4-pairs/thread
    const int brow = tid >> 1, bk = (tid & 1) << 3;

    const int lane = tid & 31, wid = tid >> 5;
    const int g = lane >> 2, t4 = lane & 3;
    const int wn = wid * (W / 4);

    float acc[2][NI][4] = {};

    {   // preload tile 0
        float4 av = *(const float4*)Aptr;
        As[0][ak4 + 0][arow] = av.x; As[0][ak4 + 1][arow] = av.y;
        As[0][ak4 + 2][arow] = av.z; As[0][ak4 + 3][arow] = av.w;
#pragma unroll
        for (int j = 0; j < W / 64; j++) {
            int r = brow + 64 * j;
            const float* bp = Bw + (size_t)r * K + bk;
            float4 b0 = *(const float4*)bp;
            float4 b1 = *(const float4*)(bp + 4);
            Bs[0][bk + 0][r] = b0.x; Bs[0][bk + 1][r] = b0.y;
            Bs[0][bk + 2][r] = b0.z; Bs[0][bk + 3][r] = b0.w;
            Bs[0][bk + 4][r] = b1.x; Bs[0][bk + 5][r] = b1.y;
            Bs[0][bk + 6][r] = b1.z; Bs[0][bk + 7][r] = b1.w;
        }
    }
    __syncthreads();

    int buf = 0;
    for (int k0 = 0; k0 < K; k0 += 16) {
        const bool notlast = (k0 + 16 < K);
        float4 pa;
        float4 pb0[W / 64], pb1[W / 64];
        if (notlast) {
            pa = *(const float4*)(Aptr + k0 + 16);
#pragma unroll
            for (int j = 0; j < W / 64; j++) {
                const float* bp = Bw + (size_t)(brow + 64 * j) * K + k0 + 16 + bk;
                pb0[j] = *(const float4*)bp;
                pb1[j] = *(const float4*)(bp + 4);
            }
        }

#pragma unroll
        for (int kk = 0; kk < 16; kk += 8) {
            unsigned ah[2][4], al[2][4];
#pragma unroll
            for (int mi = 0; mi < 2; mi++) {
                split_tf32(As[buf][kk + t4][mi * 16 + g],         ah[mi][0], al[mi][0]);
                split_tf32(As[buf][kk + t4][mi * 16 + g + 8],     ah[mi][1], al[mi][1]);
                split_tf32(As[buf][kk + t4 + 4][mi * 16 + g],     ah[mi][2], al[mi][2]);
                split_tf32(As[buf][kk + t4 + 4][mi * 16 + g + 8], ah[mi][3], al[mi][3]);
            }
#pragma unroll
            for (int ni = 0; ni < NI; ni++) {
                int c = wn + ni * 8 + g;
                unsigned bh0, bl0, bh1, bl1;
                split_tf32(Bs[buf][kk + t4][c],     bh0, bl0);
                split_tf32(Bs[buf][kk + t4 + 4][c], bh1, bl1);
#pragma unroll
                for (int mi = 0; mi < 2; mi++) {
                    float* cc = acc[mi][ni];
                    mma8(cc, al[mi][0], al[mi][1], al[mi][2], al[mi][3], bh0, bh1);
                    mma8(cc, ah[mi][0], ah[mi][1], ah[mi][2], ah[mi][3], bl0, bl1);
                    mma8(cc, ah[mi][0], ah[mi][1], ah[mi][2], ah[mi][3], bh0, bh1);
                }
            }
        }

        if (notlast) {
            int nb = buf ^ 1;
            As[nb][ak4 + 0][arow] = pa.x; As[nb][ak4 + 1][arow] = pa.y;
            As[nb][ak4 + 2][arow] = pa.z; As[nb][ak4 + 3][arow] = pa.w;
#pragma unroll
            for (int j = 0; j < W / 64; j++) {
                int r = brow + 64 * j;
                Bs[nb][bk + 0][r] = pb0[j].x; Bs[nb][bk + 1][r] = pb0[j].y;
                Bs[nb][bk + 2][r] = pb0[j].z; Bs[nb][bk + 3][r] = pb0[j].w;
                Bs[nb][bk + 4][r] = pb1[j].x; Bs[nb][bk + 5][r] = pb1[j].y;
                Bs[nb][bk + 6][r] = pb1[j].z; Bs[nb][bk + 7][r] = pb1[j].w;
            }
            __syncthreads();
            buf = nb;
        }
    }

    // ---- epilogue: bias (+res), row stats, LN, (gelu), store ----
    float s[4] = {0.f, 0.f, 0.f, 0.f}, q[4] = {0.f, 0.f, 0.f, 0.f};
#pragma unroll
    for (int mi = 0; mi < 2; mi++) {
        int lr0 = mi * 16 + g, lr1 = lr0 + 8;
#pragma unroll
        for (int ni = 0; ni < NI; ni++) {
            int c0 = wn + ni * 8 + (t4 << 1);
            float bx = bias[c0], by = bias[c0 + 1];
            float v00 = acc[mi][ni][0] + bx, v01 = acc[mi][ni][1] + by;
            float v10 = acc[mi][ni][2] + bx, v11 = acc[mi][ni][3] + by;
            if (RES) {
                float2 e0 = *(const float2*)(res + (size_t)(m0 + lr0) * W + c0);
                float2 e1 = *(const float2*)(res + (size_t)(m0 + lr1) * W + c0);
                v00 += e0.x; v01 += e0.y; v10 += e1.x; v11 += e1.y;
            }
            acc[mi][ni][0] = v00; acc[mi][ni][1] = v01;
            acc[mi][ni][2] = v10; acc[mi][ni][3] = v11;
            s[mi * 2]     += v00 + v01;       q[mi * 2]     += v00 * v00 + v01 * v01;
            s[mi * 2 + 1] += v10 + v11;       q[mi * 2 + 1] += v10 * v10 + v11 * v11;
        }
    }
#pragma unroll
    for (int i = 0; i < 4; i++) {
        s[i] += __shfl_xor_sync(0xffffffffu, s[i], 1);
        s[i] += __shfl_xor_sync(0xffffffffu, s[i], 2);
        q[i] += __shfl_xor_sync(0xffffffffu, q[i], 1);
        q[i] += __shfl_xor_sync(0xffffffffu, q[i], 2);
    }
    if (t4 == 0) {
#pragma unroll
        for (int mi = 0; mi < 2; mi++) {
            rsum[mi * 16 + g][wid]     = s[mi * 2];
            rsq [mi * 16 + g][wid]     = q[mi * 2];
            rsum[mi * 16 + g + 8][wid] = s[mi * 2 + 1];
            rsq [mi * 16 + g + 8][wid] = q[mi * 2 + 1];
        }
    }
    __syncthreads();
    if (tid < 32) {
        float fs = rsum[tid][0] + rsum[tid][1] + rsum[tid][2] + rsum[tid][3];
        float fq = rsq[tid][0] + rsq[tid][1] + rsq[tid][2] + rsq[tid][3];
        float mean = fs * (1.0f / W);
        float var = fq * (1.0f / W) - mean * mean;
        smean[tid] = mean;
        sistd[tid] = rsqrtf(var + 1e-5f);
    }
    __syncthreads();

#pragma unroll
    for (int mi = 0; mi < 2; mi++) {
        int lr0 = mi * 16 + g, lr1 = lr0 + 8;
        float m0f = smean[lr0], i0f = sistd[lr0];
        float m1f = smean[lr1], i1f = sistd[lr1];
#pragma unroll
        for (int ni = 0; ni < NI; ni++) {
            int c0 = wn + ni * 8 + (t4 << 1);
            float gx = gam[c0], gy = gam[c0 + 1];
            float bx = bet[c0], by = bet[c0 + 1];
            float o00 = gx * (acc[mi][ni][0] - m0f) * i0f + bx;
            float o01 = gy * (acc[mi][ni][1] - m0f) * i0f + by;
            float o10 = gx * (acc[mi][ni][2] - m1f) * i1f + bx;
            float o11 = gy * (acc[mi][ni][3] - m1f) * i1f + by;
            if (GELU_AFTER) {
                o00 = gelu_f(o00); o01 = gelu_f(o01);
                o10 = gelu_f(o10); o11 = gelu_f(o11);
            }
            *(float2*)(C + (size_t)(m0 + lr0) * W + c0) = make_float2(o00, o01);
            *(float2*)(C + (size_t)(m0 + lr1) * W + c0) = make_float2(o10, o11);
        }
    }
}

// ---------------- fused attention: packed bf16 QK + tf32x3 PV ---------------
__global__ void __launch_bounds__(128) attn_fused(const unsigned* __restrict__ QKh,
                                                  const unsigned* __restrict__ QKl,
                                                  const float* __restrict__ V,
                                                  float* __restrict__ O) {
    __shared__ unsigned Qh[32][72], Ql[32][72];   // [d2][qrow]
    __shared__ unsigned Kh[32][40], Kl[32][40];   // [d2][kpos]
    __shared__ __align__(16) float Vs[32][68];    // [kpos][d]
    __shared__ float Ss[64][36];                  // [q][kpos]
    __shared__ float rm[64], rl[64], rf[64];

    const int b = blockIdx.z, h = blockIdx.y, q0 = blockIdx.x << 6;
    const int tid = threadIdx.x;
    const int lane = tid & 31, wid = tid >> 5;
    const int g = lane >> 2, t4 = lane & 3;

    const unsigned* Qgh = QKh + ((size_t)(b * 512 + q0)) * 128 + h * 32;
    const unsigned* Qgl = QKl + ((size_t)(b * 512 + q0)) * 128 + h * 32;
    const unsigned* Kgh = QKh + (size_t)PTS * 128 + ((size_t)b * 512) * 128 + h * 32;
    const unsigned* Kgl = QKl + (size_t)PTS * 128 + ((size_t)b * 512) * 128 + h * 32;
    const float* Vg = V + ((size_t)b * 512) * 256 + h * 64;

    {   // stage Q tile: [d2][qrow]
        int qrow = tid >> 1, half = (tid & 1) << 4;
        const uint4* sh = (const uint4*)(Qgh + (size_t)qrow * 128 + half);
        const uint4* sl = (const uint4*)(Qgl + (size_t)qrow * 128 + half);
#pragma unroll
        for (int j = 0; j < 4; j++) {
            uint4 vh = sh[j], vl = sl[j];
            int d2 = half + j * 4;
            Qh[d2 + 0][qrow] = vh.x; Ql[d2 + 0][qrow] = vl.x;
            Qh[d2 + 1][qrow] = vh.y; Ql[d2 + 1][qrow] = vl.y;
            Qh[d2 + 2][qrow] = vh.z; Ql[d2 + 2][qrow] = vl.z;
            Qh[d2 + 3][qrow] = vh.w; Ql[d2 + 3][qrow] = vl.w;
        }
    }
    if (tid < 64) { rm[tid] = -1e30f; rl[tid] = 0.0f; }

    const int wm = (wid >> 1) << 5, wn = (wid & 1) << 5;
    const int sm = wid << 4;
    float oacc[2][4][4] = {};

    for (int kc = 0; kc < 512; kc += 32) {
        __syncthreads();
        {   // stage K packed [d2][kpos]
            int kpos = tid >> 2, seg = (tid & 3) << 3;
            const uint4* sh = (const uint4*)(Kgh + (size_t)(kc + kpos) * 128 + seg);
            const uint4* sl = (const uint4*)(Kgl + (size_t)(kc + kpos) * 128 + seg);
#pragma unroll
            for (int j = 0; j < 2; j++) {
                uint4 vh = sh[j], vl = sl[j];
                int d2 = seg + j * 4;
                Kh[d2 + 0][kpos] = vh.x; Kl[d2 + 0][kpos] = vl.x;
                Kh[d2 + 1][kpos] = vh.y; Kl[d2 + 1][kpos] = vl.y;
                Kh[d2 + 2][kpos] = vh.z; Kl[d2 + 2][kpos] = vl.z;
                Kh[d2 + 3][kpos] = vh.w; Kl[d2 + 3][kpos] = vl.w;
            }
        }
        {   // stage V floats [kpos][d]
            int i = tid >> 2, d0 = (tid & 3) << 4;
            const float* vsrc = Vg + (size_t)(kc + i) * 256 + d0;
#pragma unroll
            for (int j = 0; j < 4; j++)
                *(float4*)&Vs[i][d0 + j * 4] = *(const float4*)(vsrc + j * 4);
        }
        __syncthreads();

        // S = Q K^T (packed bf16 x3)
        float sacc[4][4] = {};
#pragma unroll
        for (int kk2 = 0; kk2 < 32; kk2 += 8) {
            int r0 = sm + g, r1 = r0 + 8;
            unsigned a0h = Qh[kk2 + t4][r0],     a0l = Ql[kk2 + t4][r0];
            unsigned a1h = Qh[kk2 + t4][r1],     a1l = Ql[kk2 + t4][r1];
            unsigned a2h = Qh[kk2 + t4 + 4][r0], a2l = Ql[kk2 + t4 + 4][r0];
            unsigned a3h = Qh[kk2 + t4 + 4][r1], a3l = Ql[kk2 + t4 + 4][r1];
#pragma unroll
            for (int ni = 0; ni < 4; ni++) {
                int c = ni * 8 + g;
                unsigned b0h = Kh[kk2 + t4][c],     b0l = Kl[kk2 + t4][c];
                unsigned b1h = Kh[kk2 + t4 + 4][c], b1l = Kl[kk2 + t4 + 4][c];
                mma16(sacc[ni], a0l, a1l, a2l, a3l, b0h, b1h);
                mma16(sacc[ni], a0h, a1h, a2h, a3h, b0l, b1l);
                mma16(sacc[ni], a0h, a1h, a2h, a3h, b0h, b1h);
            }
        }
#pragma unroll
        for (int ni = 0; ni < 4; ni++) {
            int c = (ni << 3) + (t4 << 1);
            Ss[sm + g][c]         = sacc[ni][0] * 0.125f;
            Ss[sm + g][c + 1]     = sacc[ni][1] * 0.125f;
            Ss[sm + g + 8][c]     = sacc[ni][2] * 0.125f;
            Ss[sm + g + 8][c + 1] = sacc[ni][3] * 0.125f;
        }
        __syncthreads();

        if (tid < 64) {
            float mold = rm[tid];
            float mx = mold;
#pragma unroll
            for (int j = 0; j < 32; j++) mx = fmaxf(mx, Ss[tid][j]);
            float f = __expf(mold - mx);
            float sum = 0.0f;
#pragma unroll
            for (int j = 0; j < 32; j++) {
                float p = __expf(Ss[tid][j] - mx);
                Ss[tid][j] = p;
                sum += p;
            }
            rl[tid] = rl[tid] * f + sum;
            rm[tid] = mx;
            rf[tid] = f;
        }
        __syncthreads();

#pragma unroll
        for (int mi = 0; mi < 2; mi++) {
            float f0 = rf[wm + (mi << 4) + g];
            float f1 = rf[wm + (mi << 4) + g + 8];
#pragma unroll
            for (int ni = 0; ni < 4; ni++) {
                oacc[mi][ni][0] *= f0; oacc[mi][ni][1] *= f0;
                oacc[mi][ni][2] *= f1; oacc[mi][ni][3] *= f1;
            }
        }
#pragma unroll
        for (int kk = 0; kk < 32; kk += 8) {
            unsigned ah[2][4], al[2][4];
#pragma unroll
            for (int mi = 0; mi < 2; mi++) {
                split_tf32(Ss[wm + (mi << 4) + g][kk + t4],         ah[mi][0], al[mi][0]);
                split_tf32(Ss[wm + (mi << 4) + g + 8][kk + t4],     ah[mi][1], al[mi][1]);
                split_tf32(Ss[wm + (mi << 4) + g][kk + t4 + 4],     ah[mi][2], al[mi][2]);
                split_tf32(Ss[wm + (mi << 4) + g + 8][kk + t4 + 4], ah[mi][3], al[mi][3]);
            }
#pragma unroll
            for (int ni = 0; ni < 4; ni++) {
                unsigned bh0, bh1, bl0, bl1;
                split_tf32(Vs[kk + t4][wn + ni * 8 + g],     bh0, bl0);
                split_tf32(Vs[kk + t4 + 4][wn + ni * 8 + g], bh1, bl1);
#pragma unroll
                for (int mi = 0; mi < 2; mi++) {
                    float* c = oacc[mi][ni];
                    mma8(c, al[mi][0], al[mi][1], al[mi][2], al[mi][3], bh0, bh1);
                    mma8(c, ah[mi][0], ah[mi][1], ah[mi][2], ah[mi][3], bl0, bl1);
                    mma8(c, ah[mi][0], ah[mi][1], ah[mi][2], ah[mi][3], bh0, bh1);
                }
            }
        }
    }

    float* Og = O + ((size_t)(b * 512 + q0)) * 256 + h * 64;
#pragma unroll
    for (int mi = 0; mi < 2; mi++) {
        int r0 = wm + (mi << 4) + g, r1 = r0 + 8;
        float il0 = 1.0f / rl[r0], il1 = 1.0f / rl[r1];
#pragma unroll
        for (int ni = 0; ni < 4; ni++) {
            int c = wn + (ni << 3) + (t4 << 1);
            *(float2*)(Og + (size_t)r0 * 256 + c) =
                make_float2(oacc[mi][ni][0] * il0, oacc[mi][ni][1] * il0);
            *(float2*)(Og + (size_t)r1 * 256 + c) =
                make_float2(oacc[mi][ni][2] * il1, oacc[mi][ni][3] * il1);
        }
    }
}

// ---------------- launch ----------------------------------------------------
extern "C" void kernel_launch(void* const* d_in, const int* in_sizes, int n_in,
                              void* d_out, int out_size) {
    (void)in_sizes; (void)n_in; (void)out_size;
    const float* image  = (const float*)d_in[0];
    const float* coords = (const float*)d_in[1];
    const int*   labels = (const int*)d_in[2];
    const float* pe_w   = (const float*)d_in[3];
    const float* pe_b   = (const float*)d_in[4];
    const float* temb   = (const float*)d_in[5];
    const float* fbi    = (const float*)d_in[6];
    const float* fe1_w  = (const float*)d_in[7];
    const float* fe1_b  = (const float*)d_in[8];
    const float* feln1g = (const float*)d_in[9];
    const float* feln1b = (const float*)d_in[10];
    const float* fe2_w  = (const float*)d_in[11];
    const float* fe2_b  = (const float*)d_in[12];
    const float* feln2g = (const float*)d_in[13];
    const float* feln2b = (const float*)d_in[14];
    const float* in_w   = (const float*)d_in[15];
    const float* in_b   = (const float*)d_in[16];
    const float* ao_w   = (const float*)d_in[17];
    const float* ao_b   = (const float*)d_in[18];
    const float* n1_g   = (const float*)d_in[19];
    const float* n1_b   = (const float*)d_in[20];
    const float* f1_w   = (const float*)d_in[21];
    const float* f1_b   = (const float*)d_in[22];
    const float* f2_w   = (const float*)d_in[23];
    const float* f2_b   = (const float*)d_in[24];
    const float* n2_g   = (const float*)d_in[25];
    const float* n2_b   = (const float*)d_in[26];
    const float* op_w   = (const float*)d_in[27];
    const float* op_b   = (const float*)d_in[28];
    float* out = (float*)d_out;

    float *p_pe, *p_spatial, *p_feat, *p_h1, *p_freq;
    float *p_v, *p_o, *p_x, *p_ffh, *p_x2;
    unsigned *p_qkh, *p_qkl;
    cudaGetSymbolAddress((void**)&p_pe, g_pe);
    cudaGetSymbolAddress((void**)&p_spatial, g_spatial);
    cudaGetSymbolAddress((void**)&p_feat, g_feat);
    cudaGetSymbolAddress((void**)&p_h1, g_h1);
    cudaGetSymbolAddress((void**)&p_freq, g_freq);
    cudaGetSymbolAddress((void**)&p_qkh, g_qkh);
    cudaGetSymbolAddress((void**)&p_qkl, g_qkl);
    cudaGetSymbolAddress((void**)&p_v, g_v);
    cudaGetSymbolAddress((void**)&p_o, g_o);
    cudaGetSymbolAddress((void**)&p_x, g_x);
    cudaGetSymbolAddress((void**)&p_ffh, g_ffh);
    cudaGetSymbolAddress((void**)&p_x2, g_x2);

    // 1) sinusoidal PE
    pe_kernel<<<PTS, 128>>>(coords, p_pe);
    // 2) spatial = PE @ pe_w^T + pe_b + type_emb[label]
    gemm_tc<2><<<dim3(4, 64, 1), 128>>>(p_pe, pe_w, pe_b, p_spatial,
        256, 256, 256, 256, labels, temb, nullptr, nullptr, nullptr);
    // 3) patch FFT features
    fft_feat_kernel<<<PTS, 256>>>(image, coords, fbi, p_feat);
    // 4) freq MLP (GEMM+LN fused)
    gemm_ln<128, false, true><<<128, 128>>>(p_feat, fe1_w, fe1_b, nullptr,
        feln1g, feln1b, p_h1, 16, 16);
    gemm_ln<256, false, false><<<128, 128>>>(p_h1, fe2_w, fe2_b, nullptr,
        feln2g, feln2b, p_freq, 128, 128);
    // 5) fused Q/K/V projections: z=0,1 -> packed bf16 Q/K; z=2 -> float V
    gemm_tc<4><<<dim3(4, 64, 3), 128>>>(p_spatial, in_w, in_b, p_v,
        256, 256, 256, 256, nullptr, nullptr, p_freq, p_qkh, p_qkl);
    // 6) fused attention
    attn_fused<<<dim3(8, 4, 8), 128>>>(p_qkh, p_qkl, p_v, p_o);
    // 7) attn out proj + residual + LN (fused)
    gemm_ln<256, true, false><<<128, 128>>>(p_o, ao_w, ao_b, p_spatial,
        n1_g, n1_b, p_x, 256, 256);
    // 8) FFN
    gemm_tc<1><<<dim3(8, 64, 1), 128>>>(p_x, f1_w, f1_b, p_ffh,
        256, 256, 256, 512, nullptr, nullptr, nullptr, nullptr, nullptr);
    gemm_ln<256, true, false><<<128, 128>>>(p_ffh, f2_w, f2_b, p_x,
        n2_g, n2_b, p_x2, 512, 512);
    // 9) output projection
    gemm_tc<0><<<dim3(4, 64, 1), 128>>>(p_x2, op_w, op_b, out,
        256, 256, 256, 256, nullptr, nullptr, nullptr, nullptr, nullptr);
}